// round 2
// baseline (speedup 1.0000x reference)
#include <cuda_runtime.h>
#include <math.h>

#define BB   16
#define CC   256
#define CI   128
#define HWN  4096
#define NP   1024

// ---------------- scratch (static device globals; no allocation) ----------------
__device__ float d_theta[BB * HWN * CI];   // [b][n][ci]
__device__ float d_gf[BB * HWN * CI];      // g conv full res
__device__ float d_pf[BB * HWN * CI];      // phi conv full res
__device__ float d_gp[BB * NP * CI];       // g pooled  [b][m][ci]
__device__ float d_pp[BB * NP * CI];       // phi pooled [b][m][ci]
__device__ float d_yy[BB * HWN * CI];      // attention out [b][n][ci]
__device__ float d_wy[BB * CC * HWN];      // W conv out [b][co][n]
__device__ float d_mean[CC];
__device__ float d_rstd[CC];

// ---------------- conv1x1: out[b][n][ci] = sum_c w[ci][c]*x[b][c][n] + bias[ci] ----------------
// grid (HWN/64, B), block 256. Tile: 64 n x 128 ci, K chunks of 16.
__global__ __launch_bounds__(256) void conv1x1_k(const float* __restrict__ x,
                                                 const float* __restrict__ w,
                                                 const float* __restrict__ bias,
                                                 float* __restrict__ out) {
    __shared__ float xs[16][64];    // [k][n]
    __shared__ float ws[16][128];   // [k][ci]
    const int b = blockIdx.y, n0 = blockIdx.x * 64;
    const int tid = threadIdx.x, tx = tid & 15, ty = tid >> 4;
    const float* xb = x + (size_t)b * CC * HWN;

    float acc[4][8];
#pragma unroll
    for (int i = 0; i < 4; ++i)
#pragma unroll
        for (int j = 0; j < 8; ++j) acc[i][j] = 0.f;

    for (int c0 = 0; c0 < CC; c0 += 16) {
        {   // x tile: 16k x 64n = 256 float4, one per thread
            const int kk = tid >> 4, n4 = tid & 15;
            *(float4*)&xs[kk][n4 * 4] =
                *(const float4*)&xb[(size_t)(c0 + kk) * HWN + n0 + n4 * 4];
        }
#pragma unroll
        for (int it = 0; it < 2; ++it) {    // w tile transpose-load, coalesced along c
            const int li = tid + it * 256;
            const int ci = li >> 2, q = li & 3;
            float4 w4 = *(const float4*)&w[(size_t)ci * CC + c0 + q * 4];
            ws[q * 4 + 0][ci] = w4.x; ws[q * 4 + 1][ci] = w4.y;
            ws[q * 4 + 2][ci] = w4.z; ws[q * 4 + 3][ci] = w4.w;
        }
        __syncthreads();
#pragma unroll
        for (int k = 0; k < 16; ++k) {
            float4 a  = *(const float4*)&xs[k][ty * 4];
            float4 b0 = *(const float4*)&ws[k][tx * 8];
            float4 b1 = *(const float4*)&ws[k][tx * 8 + 4];
            float av[4] = {a.x, a.y, a.z, a.w};
            float bv[8] = {b0.x, b0.y, b0.z, b0.w, b1.x, b1.y, b1.z, b1.w};
#pragma unroll
            for (int i = 0; i < 4; ++i)
#pragma unroll
                for (int j = 0; j < 8; ++j) acc[i][j] += av[i] * bv[j];
        }
        __syncthreads();
    }
#pragma unroll
    for (int i = 0; i < 4; ++i) {
        const int n = n0 + ty * 4 + i;
        float* op = out + (size_t)b * HWN * CI + (size_t)n * CI + tx * 8;
        float4 o0 = make_float4(acc[i][0] + bias[tx * 8 + 0], acc[i][1] + bias[tx * 8 + 1],
                                acc[i][2] + bias[tx * 8 + 2], acc[i][3] + bias[tx * 8 + 3]);
        float4 o1 = make_float4(acc[i][4] + bias[tx * 8 + 4], acc[i][5] + bias[tx * 8 + 5],
                                acc[i][6] + bias[tx * 8 + 6], acc[i][7] + bias[tx * 8 + 7]);
        *(float4*)op = o0;
        *(float4*)(op + 4) = o1;
    }
}

// ---------------- 2x2 maxpool over spatial, channel-last ----------------
__global__ __launch_bounds__(256) void pool_k(const float* __restrict__ in,
                                              float* __restrict__ out) {
    const int gi = blockIdx.x * 256 + threadIdx.x;      // < B*NP*32 (float4 units)
    const int b = gi / (NP * 32);
    const int rem = gi - b * (NP * 32);
    const int m = rem >> 5, k4 = rem & 31;
    const int ph = m >> 5, pw = m & 31;
    const int n00 = ph * 128 + pw * 2;
    const float* ib = in + (size_t)b * HWN * CI + (size_t)n00 * CI + k4 * 4;
    float4 v0 = *(const float4*)ib;
    float4 v1 = *(const float4*)(ib + CI);
    float4 v2 = *(const float4*)(ib + 64 * CI);
    float4 v3 = *(const float4*)(ib + 65 * CI);
    float4 r;
    r.x = fmaxf(fmaxf(v0.x, v1.x), fmaxf(v2.x, v3.x));
    r.y = fmaxf(fmaxf(v0.y, v1.y), fmaxf(v2.y, v3.y));
    r.z = fmaxf(fmaxf(v0.z, v1.z), fmaxf(v2.z, v3.z));
    r.w = fmaxf(fmaxf(v0.w, v1.w), fmaxf(v2.w, v3.w));
    *(float4*)&out[(size_t)b * NP * CI + (size_t)m * CI + k4 * 4] = r;
}

// ---------------- fused attention: y = softmax(theta . phi^T) . g ----------------
// Q = theta [b][4096][128], K = phi pooled [b][1024][128], V = g pooled.
// grid (HWN/64, B), block 256. Flash-style online softmax, KV tiles of 64.
__global__ __launch_bounds__(256) void attn_k(const float* __restrict__ q,
                                              const float* __restrict__ kp,
                                              const float* __restrict__ gp,
                                              float* __restrict__ y) {
    extern __shared__ float sm[];
    float* qs = sm;                 // 64 x 132
    float* ks = qs + 64 * 132;      // 64 x 132
    float* gs = ks + 64 * 132;      // 64 x 128
    float* ps = gs + 64 * 128;      // 64 x 68
    const int b = blockIdx.y, n0 = blockIdx.x * 64;
    const int tid = threadIdx.x, tx = tid & 15, ty = tid >> 4;
    const float* qb = q  + (size_t)b * HWN * CI;
    const float* kb = kp + (size_t)b * NP * CI;
    const float* gb = gp + (size_t)b * NP * CI;

#pragma unroll
    for (int i = 0; i < 8; ++i) {
        const int idx = tid + i * 256;
        const int row = idx >> 5, k4 = idx & 31;
        *(float4*)&qs[row * 132 + k4 * 4] =
            *(const float4*)&qb[(size_t)(n0 + row) * CI + k4 * 4];
    }

    float acc[4][8];
#pragma unroll
    for (int i = 0; i < 4; ++i)
#pragma unroll
        for (int j = 0; j < 8; ++j) acc[i][j] = 0.f;
    float mrow[4] = {-1e30f, -1e30f, -1e30f, -1e30f};
    float lrow[4] = {0.f, 0.f, 0.f, 0.f};

    for (int jt = 0; jt < 16; ++jt) {
        const int m0 = jt * 64;
#pragma unroll
        for (int i = 0; i < 8; ++i) {
            const int idx = tid + i * 256;
            const int row = idx >> 5, k4 = idx & 31;
            *(float4*)&ks[row * 132 + k4 * 4] =
                *(const float4*)&kb[(size_t)(m0 + row) * CI + k4 * 4];
            *(float4*)&gs[row * 128 + k4 * 4] =
                *(const float4*)&gb[(size_t)(m0 + row) * CI + k4 * 4];
        }
        __syncthreads();

        // S = Q Kt  (64x64, thread owns 4 rows x 4 cols)
        float s[4][4];
#pragma unroll
        for (int i = 0; i < 4; ++i)
#pragma unroll
            for (int j = 0; j < 4; ++j) s[i][j] = 0.f;
#pragma unroll 8
        for (int k4 = 0; k4 < 32; ++k4) {
            float4 qv[4], kv[4];
#pragma unroll
            for (int i = 0; i < 4; ++i)
                qv[i] = *(const float4*)&qs[(ty * 4 + i) * 132 + k4 * 4];
#pragma unroll
            for (int j = 0; j < 4; ++j)
                kv[j] = *(const float4*)&ks[(tx * 4 + j) * 132 + k4 * 4];
#pragma unroll
            for (int i = 0; i < 4; ++i)
#pragma unroll
                for (int j = 0; j < 4; ++j)
                    s[i][j] += qv[i].x * kv[j].x + qv[i].y * kv[j].y +
                               qv[i].z * kv[j].z + qv[i].w * kv[j].w;
        }

        // online softmax (row stats replicated across the 16 tx lanes per row)
#pragma unroll
        for (int i = 0; i < 4; ++i) {
            float tm = fmaxf(fmaxf(s[i][0], s[i][1]), fmaxf(s[i][2], s[i][3]));
#pragma unroll
            for (int off = 8; off; off >>= 1)
                tm = fmaxf(tm, __shfl_xor_sync(0xffffffffu, tm, off));
            const float mnew = fmaxf(mrow[i], tm);
            const float scale = __expf(mrow[i] - mnew);
            float psum = 0.f;
#pragma unroll
            for (int j = 0; j < 4; ++j) { s[i][j] = __expf(s[i][j] - mnew); psum += s[i][j]; }
#pragma unroll
            for (int off = 8; off; off >>= 1)
                psum += __shfl_xor_sync(0xffffffffu, psum, off);
            lrow[i] = lrow[i] * scale + psum;
            mrow[i] = mnew;
#pragma unroll
            for (int jj = 0; jj < 8; ++jj) acc[i][jj] *= scale;
            *(float4*)&ps[(ty * 4 + i) * 68 + tx * 4] =
                make_float4(s[i][0], s[i][1], s[i][2], s[i][3]);
        }
        __syncthreads();

        // acc += P * G  (thread owns 4 rows x 8 d-cols)
#pragma unroll 4
        for (int m4 = 0; m4 < 16; ++m4) {
            float pr[4][4];
#pragma unroll
            for (int i = 0; i < 4; ++i) {
                float4 t = *(const float4*)&ps[(ty * 4 + i) * 68 + m4 * 4];
                pr[i][0] = t.x; pr[i][1] = t.y; pr[i][2] = t.z; pr[i][3] = t.w;
            }
#pragma unroll
            for (int u = 0; u < 4; ++u) {
                const int m = m4 * 4 + u;
                float4 ga = *(const float4*)&gs[m * 128 + tx * 8];
                float4 gb4 = *(const float4*)&gs[m * 128 + tx * 8 + 4];
#pragma unroll
                for (int i = 0; i < 4; ++i) {
                    const float p = pr[i][u];
                    acc[i][0] += p * ga.x;  acc[i][1] += p * ga.y;
                    acc[i][2] += p * ga.z;  acc[i][3] += p * ga.w;
                    acc[i][4] += p * gb4.x; acc[i][5] += p * gb4.y;
                    acc[i][6] += p * gb4.z; acc[i][7] += p * gb4.w;
                }
            }
        }
        __syncthreads();
    }

#pragma unroll
    for (int i = 0; i < 4; ++i) {
        const int r = n0 + ty * 4 + i;
        const float inv = 1.f / lrow[i];
        float* op = y + (size_t)b * HWN * CI + (size_t)r * CI + tx * 8;
        *(float4*)op = make_float4(acc[i][0] * inv, acc[i][1] * inv,
                                   acc[i][2] * inv, acc[i][3] * inv);
        *(float4*)(op + 4) = make_float4(acc[i][4] * inv, acc[i][5] * inv,
                                         acc[i][6] * inv, acc[i][7] * inv);
    }
}

// ---------------- W conv: wy[b][co][n] = sum_ci W_w[co][ci]*y[b][n][ci] + W_b[co] ----------------
// grid (HWN/64, C/64, B), block 256. K=128 single pass.
__global__ __launch_bounds__(256) void wconv_k(const float* __restrict__ y,
                                               const float* __restrict__ w,
                                               const float* __restrict__ bias,
                                               float* __restrict__ out) {
    extern __shared__ float sm[];
    float* as = sm;              // 64 x 132 (W rows)
    float* ys = sm + 64 * 132;   // 64 x 132 (y rows)
    const int n0 = blockIdx.x * 64, co0 = blockIdx.y * 64, b = blockIdx.z;
    const int tid = threadIdx.x, tx = tid & 15, ty = tid >> 4;

#pragma unroll
    for (int i = 0; i < 8; ++i) {
        const int idx = tid + i * 256;
        const int row = idx >> 5, k4 = idx & 31;
        *(float4*)&as[row * 132 + k4 * 4] =
            *(const float4*)&w[(size_t)(co0 + row) * CI + k4 * 4];
        *(float4*)&ys[row * 132 + k4 * 4] =
            *(const float4*)&y[(size_t)b * HWN * CI + (size_t)(n0 + row) * CI + k4 * 4];
    }
    __syncthreads();

    float acc[4][4];
#pragma unroll
    for (int i = 0; i < 4; ++i)
#pragma unroll
        for (int j = 0; j < 4; ++j) acc[i][j] = 0.f;
#pragma unroll 8
    for (int k4 = 0; k4 < 32; ++k4) {
        float4 av[4], bv[4];
#pragma unroll
        for (int i = 0; i < 4; ++i)
            av[i] = *(const float4*)&as[(ty * 4 + i) * 132 + k4 * 4];
#pragma unroll
        for (int j = 0; j < 4; ++j)
            bv[j] = *(const float4*)&ys[(tx * 4 + j) * 132 + k4 * 4];
#pragma unroll
        for (int i = 0; i < 4; ++i)
#pragma unroll
            for (int j = 0; j < 4; ++j)
                acc[i][j] += av[i].x * bv[j].x + av[i].y * bv[j].y +
                             av[i].z * bv[j].z + av[i].w * bv[j].w;
    }
#pragma unroll
    for (int i = 0; i < 4; ++i) {
        const int co = co0 + ty * 4 + i;
        const float bb = bias[co];
        *(float4*)&out[(size_t)b * CC * HWN + (size_t)co * HWN + n0 + tx * 4] =
            make_float4(acc[i][0] + bb, acc[i][1] + bb, acc[i][2] + bb, acc[i][3] + bb);
    }
}

// ---------------- BN stats (deterministic, double accumulation) ----------------
__global__ __launch_bounds__(256) void bnstats_k(const float* __restrict__ wy) {
    __shared__ double rs[256], rs2[256];
    const int co = blockIdx.x, tid = threadIdx.x;
    double s = 0.0, s2 = 0.0;
    for (int i = tid; i < BB * HWN; i += 256) {
        const int bb = i >> 12, n = i & 4095;
        const float v = wy[(size_t)bb * CC * HWN + (size_t)co * HWN + n];
        s += (double)v; s2 += (double)v * (double)v;
    }
    rs[tid] = s; rs2[tid] = s2;
    __syncthreads();
    for (int o = 128; o; o >>= 1) {
        if (tid < o) { rs[tid] += rs[tid + o]; rs2[tid] += rs2[tid + o]; }
        __syncthreads();
    }
    if (tid == 0) {
        const double cnt = (double)(BB * HWN);
        const double mean = rs[0] / cnt;
        const double var = rs2[0] / cnt - mean * mean;
        d_mean[co] = (float)mean;
        d_rstd[co] = (float)rsqrt(var + 1e-5);
    }
}

// ---------------- normalize + residual + pack output ----------------
__global__ __launch_bounds__(256) void final_k(const float* __restrict__ wy,
                                               const float* __restrict__ x,
                                               const float* __restrict__ gamma,
                                               const float* __restrict__ beta,
                                               const float* __restrict__ inp0,
                                               float* __restrict__ out, int off) {
    const int gi = blockIdx.x * 256 + threadIdx.x;     // < B*C*HWN/4
    if (gi == 0 && off == 1) out[0] = inp0[0];
    const int base = gi * 4;
    const int co = (base >> 12) & 255;
    const float a = d_rstd[co] * gamma[co];
    const float bconst = beta[co] - d_mean[co] * a;
    float4 wv = *(const float4*)&wy[base];
    float4 xv = *(const float4*)&x[base];
    float* o = out + off + base;
    o[0] = wv.x * a + bconst + xv.x;
    o[1] = wv.y * a + bconst + xv.y;
    o[2] = wv.z * a + bconst + xv.z;
    o[3] = wv.w * a + bconst + xv.w;
}

// ---------------- host launcher ----------------
extern "C" void kernel_launch(void* const* d_in, const int* in_sizes, int n_in,
                              void* d_out, int out_size) {
    const float* inp0 = (const float*)d_in[0];
    const float* x    = (const float*)d_in[1];
    const float* g_w  = (const float*)d_in[2];
    const float* g_b  = (const float*)d_in[3];
    const float* th_w = (const float*)d_in[4];
    const float* th_b = (const float*)d_in[5];
    const float* ph_w = (const float*)d_in[6];
    const float* ph_b = (const float*)d_in[7];
    const float* W_w  = (const float*)d_in[8];
    const float* W_b  = (const float*)d_in[9];
    const float* gam  = (const float*)d_in[10];
    const float* bet  = (const float*)d_in[11];
    float* out = (float*)d_out;

    float *p_theta, *p_gf, *p_pf, *p_gp, *p_pp, *p_yy, *p_wy;
    cudaGetSymbolAddress((void**)&p_theta, d_theta);
    cudaGetSymbolAddress((void**)&p_gf, d_gf);
    cudaGetSymbolAddress((void**)&p_pf, d_pf);
    cudaGetSymbolAddress((void**)&p_gp, d_gp);
    cudaGetSymbolAddress((void**)&p_pp, d_pp);
    cudaGetSymbolAddress((void**)&p_yy, d_yy);
    cudaGetSymbolAddress((void**)&p_wy, d_wy);

    const int ATTN_SMEM  = (64 * 132 * 2 + 64 * 128 + 64 * 68) * 4;  // 117760
    const int WCONV_SMEM = (64 * 132 * 2) * 4;                        // 67584
    cudaFuncSetAttribute(attn_k,  cudaFuncAttributeMaxDynamicSharedMemorySize, ATTN_SMEM);
    cudaFuncSetAttribute(wconv_k, cudaFuncAttributeMaxDynamicSharedMemorySize, WCONV_SMEM);

    dim3 convGrid(HWN / 64, BB);
    conv1x1_k<<<convGrid, 256>>>(x, th_w, th_b, p_theta);
    conv1x1_k<<<convGrid, 256>>>(x, g_w,  g_b,  p_gf);
    conv1x1_k<<<convGrid, 256>>>(x, ph_w, ph_b, p_pf);

    pool_k<<<(BB * NP * 32) / 256, 256>>>(p_gf, p_gp);
    pool_k<<<(BB * NP * 32) / 256, 256>>>(p_pf, p_pp);

    attn_k<<<dim3(HWN / 64, BB), 256, ATTN_SMEM>>>(p_theta, p_pp, p_gp, p_yy);

    wconv_k<<<dim3(HWN / 64, CC / 64, BB), 256, WCONV_SMEM>>>(p_yy, W_w, W_b, p_wy);

    bnstats_k<<<CC, 256>>>(p_wy);

    const int total = BB * CC * HWN;
    const int off = (out_size > total) ? (out_size - total) : 0;
    final_k<<<total / 4 / 256, 256>>>(p_wy, x, gam, bet, inp0, out, off);
}

// round 5
// speedup vs baseline: 1.8247x; 1.8247x over previous
#include <cuda_runtime.h>
#include <math.h>

#define BB   16
#define CC   256
#define CI   128
#define HWN  4096
#define NP   1024

__device__ float d_xt[BB * HWN * CC];      // x transposed [b][n][c]
__device__ float d_theta[BB * HWN * CI];
__device__ float d_gf[BB * HWN * CI];
__device__ float d_pf[BB * HWN * CI];
__device__ float d_gp[BB * NP * CI];
__device__ float d_pp[BB * NP * CI];
__device__ float d_yy[BB * HWN * CI];
__device__ float d_wy[BB * HWN * CC];      // channel-last [b][n][co]
__device__ float d_part[2][256][256];
__device__ float d_mean[CC];
__device__ float d_rstd[CC];

__device__ __forceinline__ unsigned ftf(float x) {
    unsigned u; asm("cvt.rna.tf32.f32 %0,%1;" : "=r"(u) : "f"(x)); return u;
}
// mma.m16n8k8 tf32 fragment layout (PTX ISA):
//   a0=A[g][t]  a1=A[g+8][t]  a2=A[g][t+4]  a3=A[g+8][t+4]
//   b0=B[n=g][k=t]  b1=B[n=g][k=t+4]
//   c0=C[g][2t] c1=C[g][2t+1] c2=C[g+8][2t] c3=C[g+8][2t+1]
__device__ __forceinline__ void mma8(float* c, unsigned a0, unsigned a1, unsigned a2, unsigned a3,
                                     unsigned b0, unsigned b1) {
    asm volatile("mma.sync.aligned.m16n8k8.row.col.f32.tf32.tf32.f32 "
                 "{%0,%1,%2,%3},{%4,%5,%6,%7},{%8,%9},{%0,%1,%2,%3};"
                 : "+f"(c[0]), "+f"(c[1]), "+f"(c[2]), "+f"(c[3])
                 : "r"(a0), "r"(a1), "r"(a2), "r"(a3), "r"(b0), "r"(b1));
}

// ---- x[b][c][n] -> xt[b][n][c] ----
__global__ __launch_bounds__(256) void transpose_k(const float* __restrict__ x,
                                                   float* __restrict__ xt) {
    __shared__ float tl[32][33];
    const int b = blockIdx.z, c0 = blockIdx.y * 32, n0 = blockIdx.x * 32;
    const int tx = threadIdx.x, ty = threadIdx.y;
    const float* xb = x + (size_t)b * CC * HWN;
    float* xo = xt + (size_t)b * HWN * CC;
#pragma unroll
    for (int i = 0; i < 4; ++i)
        tl[ty + 8 * i][tx] = xb[(size_t)(c0 + ty + 8 * i) * HWN + n0 + tx];
    __syncthreads();
#pragma unroll
    for (int i = 0; i < 4; ++i)
        xo[(size_t)(n0 + ty + 8 * i) * CC + c0 + tx] = tl[tx][ty + 8 * i];
}

// ---- GEMM: C[row][col] = A[row][:K].B[col][:K] + bias[col]; tile 128x128, 8 warps ----
template<int K, bool PRECISE>
__global__ __launch_bounds__(256) void gemm_k(const float* __restrict__ A, long aStride,
                                              const float* __restrict__ B,
                                              const float* __restrict__ bias,
                                              float* __restrict__ C, int ldc, long cStride) {
    extern __shared__ float smc[];
    const int LD = PRECISE ? 68 : 36;
    unsigned* Asu = (unsigned*)smc;
    unsigned* Bsu = Asu + 128 * LD;
    const int b = blockIdx.z;
    const int row0 = blockIdx.x * 128, col0 = blockIdx.y * 128;
    const int tid = threadIdx.x, lane = tid & 31, wid = tid >> 5;
    const int g = lane >> 2, t = lane & 3;
    const int wm = (wid & 3) * 32, wn = (wid >> 2) * 64;
    const float* Ab = A + (size_t)b * aStride;
    float* Cb = C + (size_t)b * cStride;

    float acc[2][8][4];
#pragma unroll
    for (int mt = 0; mt < 2; ++mt)
#pragma unroll
        for (int j = 0; j < 8; ++j)
#pragma unroll
            for (int q = 0; q < 4; ++q) acc[mt][j][q] = 0.f;

    for (int c0 = 0; c0 < K; c0 += 32) {
        __syncthreads();
#pragma unroll
        for (int i = 0; i < 4; ++i) {
            const int id = tid + i * 256;
            const int row = id >> 3, kq = id & 7;
            float4 va = *(const float4*)&Ab[(size_t)(row0 + row) * K + c0 + kq * 4];
            float4 vb = *(const float4*)&B[(size_t)(col0 + row) * K + c0 + kq * 4];
            if (PRECISE) {
                unsigned h0 = ftf(va.x), h1 = ftf(va.y), h2 = ftf(va.z), h3 = ftf(va.w);
                *(uint4*)&Asu[row * 68 + kq * 8] =
                    make_uint4(h0, ftf(va.x - __uint_as_float(h0)),
                               h1, ftf(va.y - __uint_as_float(h1)));
                *(uint4*)&Asu[row * 68 + kq * 8 + 4] =
                    make_uint4(h2, ftf(va.z - __uint_as_float(h2)),
                               h3, ftf(va.w - __uint_as_float(h3)));
                unsigned e0 = ftf(vb.x), e1 = ftf(vb.y), e2 = ftf(vb.z), e3 = ftf(vb.w);
                *(uint4*)&Bsu[row * 68 + kq * 8] =
                    make_uint4(e0, ftf(vb.x - __uint_as_float(e0)),
                               e1, ftf(vb.y - __uint_as_float(e1)));
                *(uint4*)&Bsu[row * 68 + kq * 8 + 4] =
                    make_uint4(e2, ftf(vb.z - __uint_as_float(e2)),
                               e3, ftf(vb.w - __uint_as_float(e3)));
            } else {
                *(uint4*)&Asu[row * 36 + kq * 4] =
                    make_uint4(ftf(va.x), ftf(va.y), ftf(va.z), ftf(va.w));
                *(uint4*)&Bsu[row * 36 + kq * 4] =
                    make_uint4(ftf(vb.x), ftf(vb.y), ftf(vb.z), ftf(vb.w));
            }
        }
        __syncthreads();
#pragma unroll
        for (int kk = 0; kk < 4; ++kk) {
            if (PRECISE) {
                // entry pair (hi,lo) of k at offset 2k; k = kk*8 + t, k+4 at +8
                unsigned ah[2][4], al[2][4];
#pragma unroll
                for (int mt = 0; mt < 2; ++mt) {
                    const int rb = (wm + mt * 16 + g) * 68 + 2 * (kk * 8 + t);
                    uint2 p0 = *(uint2*)&Asu[rb];               // A[g][k]
                    uint2 p1 = *(uint2*)&Asu[rb + 8 * 68];      // A[g+8][k]
                    uint2 p2 = *(uint2*)&Asu[rb + 8];           // A[g][k+4]
                    uint2 p3 = *(uint2*)&Asu[rb + 8 * 68 + 8];  // A[g+8][k+4]
                    ah[mt][0] = p0.x; al[mt][0] = p0.y;
                    ah[mt][1] = p1.x; al[mt][1] = p1.y;
                    ah[mt][2] = p2.x; al[mt][2] = p2.y;
                    ah[mt][3] = p3.x; al[mt][3] = p3.y;
                }
#pragma unroll
                for (int j = 0; j < 8; ++j) {
                    const int nb = (wn + 8 * j + g) * 68 + 2 * (kk * 8 + t);
                    uint2 q0 = *(uint2*)&Bsu[nb];       // B[col][k] (hi,lo)
                    uint2 q1 = *(uint2*)&Bsu[nb + 8];   // B[col][k+4]
#pragma unroll
                    for (int mt = 0; mt < 2; ++mt) {
                        mma8(acc[mt][j], ah[mt][0], ah[mt][1], ah[mt][2], ah[mt][3], q0.x, q1.x);
                        mma8(acc[mt][j], ah[mt][0], ah[mt][1], ah[mt][2], ah[mt][3], q0.y, q1.y);
                        mma8(acc[mt][j], al[mt][0], al[mt][1], al[mt][2], al[mt][3], q0.x, q1.x);
                    }
                }
            } else {
                unsigned a[2][4];
#pragma unroll
                for (int mt = 0; mt < 2; ++mt) {
                    const int rb = (wm + mt * 16 + g) * 36 + kk * 8 + t;
                    a[mt][0] = Asu[rb];                 // A[g][k]
                    a[mt][1] = Asu[rb + 8 * 36];        // A[g+8][k]
                    a[mt][2] = Asu[rb + 4];             // A[g][k+4]
                    a[mt][3] = Asu[rb + 8 * 36 + 4];    // A[g+8][k+4]
                }
#pragma unroll
                for (int j = 0; j < 8; ++j) {
                    const int nb = (wn + 8 * j + g) * 36 + kk * 8 + t;
                    unsigned b0 = Bsu[nb], b1 = Bsu[nb + 4];
#pragma unroll
                    for (int mt = 0; mt < 2; ++mt)
                        mma8(acc[mt][j], a[mt][0], a[mt][1], a[mt][2], a[mt][3], b0, b1);
                }
            }
        }
    }
#pragma unroll
    for (int mt = 0; mt < 2; ++mt)
#pragma unroll
        for (int j = 0; j < 8; ++j) {
            const int col = col0 + wn + 8 * j + 2 * t;
            float2 bv = *(const float2*)&bias[col];
            const int r = row0 + wm + mt * 16 + g;
            *(float2*)&Cb[(size_t)r * ldc + col] =
                make_float2(acc[mt][j][0] + bv.x, acc[mt][j][1] + bv.y);
            *(float2*)&Cb[(size_t)(r + 8) * ldc + col] =
                make_float2(acc[mt][j][2] + bv.x, acc[mt][j][3] + bv.y);
        }
}

// ---- 2x2 maxpool, channel-last ----
__global__ __launch_bounds__(256) void pool_k(const float* __restrict__ in,
                                              float* __restrict__ out) {
    const int gi = blockIdx.x * 256 + threadIdx.x;
    const int b = gi / (NP * 32);
    const int rem = gi - b * (NP * 32);
    const int m = rem >> 5, k4 = rem & 31;
    const int ph = m >> 5, pw = m & 31;
    const int n00 = ph * 128 + pw * 2;
    const float* ib = in + (size_t)b * HWN * CI + (size_t)n00 * CI + k4 * 4;
    float4 v0 = *(const float4*)ib;
    float4 v1 = *(const float4*)(ib + CI);
    float4 v2 = *(const float4*)(ib + 64 * CI);
    float4 v3 = *(const float4*)(ib + 65 * CI);
    float4 r;
    r.x = fmaxf(fmaxf(v0.x, v1.x), fmaxf(v2.x, v3.x));
    r.y = fmaxf(fmaxf(v0.y, v1.y), fmaxf(v2.y, v3.y));
    r.z = fmaxf(fmaxf(v0.z, v1.z), fmaxf(v2.z, v3.z));
    r.w = fmaxf(fmaxf(v0.w, v1.w), fmaxf(v2.w, v3.w));
    *(float4*)&out[(size_t)b * NP * CI + (size_t)m * CI + k4 * 4] = r;
}

// ---- fused attention, tf32 mma. 128 q-rows/CTA, 8 warps x 16 rows, KV tiles 64. ----
__global__ __launch_bounds__(256) void attn_k(const float* __restrict__ q,
                                              const float* __restrict__ kp,
                                              const float* __restrict__ gp,
                                              float* __restrict__ y) {
    extern __shared__ float sm[];
    float* qs = sm;                              // 128 x 132 fp32
    unsigned* ksu = (unsigned*)(qs + 128 * 132); // 64 x 264 hi/lo interleaved
    unsigned* vsu = ksu + 64 * 264;              // 8192: interleaved V
    unsigned* psu = vsu + 8192;                  // 128 x 68 tf32
    const int b = blockIdx.y, n0 = blockIdx.x * 128;
    const int tid = threadIdx.x, lane = tid & 31, wid = tid >> 5;
    const int g = lane >> 2, t = lane & 3;
    const int wrow = wid * 16;
    const float* qb = q  + (size_t)b * HWN * CI;
    const float* kb = kp + (size_t)b * NP * CI;
    const float* gb = gp + (size_t)b * NP * CI;

#pragma unroll
    for (int i = 0; i < 16; ++i) {
        const int id = tid + i * 256;
        const int row = id >> 5, k4 = id & 31;
        *(float4*)&qs[row * 132 + k4 * 4] =
            *(const float4*)&qb[(size_t)(n0 + row) * CI + k4 * 4];
    }

    float o[16][4];
#pragma unroll
    for (int j = 0; j < 16; ++j)
#pragma unroll
        for (int qd = 0; qd < 4; ++qd) o[j][qd] = 0.f;
    float mr[2] = {-1e30f, -1e30f}, lr[2] = {0.f, 0.f};

    for (int iter = 0; iter < 16; ++iter) {
        const int m0 = iter * 64;
        __syncthreads();
        // stage K/V tile: 64 rows x 32 float4 = 2048 tasks, 8 iterations
#pragma unroll
        for (int i = 0; i < 8; ++i) {
            const int id = tid + i * 256;
            const int row = id >> 5, kq = id & 31;
            float4 v = *(const float4*)&kb[(size_t)(m0 + row) * CI + kq * 4];
            unsigned h0 = ftf(v.x), h1 = ftf(v.y), h2 = ftf(v.z), h3 = ftf(v.w);
            *(uint4*)&ksu[row * 264 + kq * 8] =
                make_uint4(h0, ftf(v.x - __uint_as_float(h0)),
                           h1, ftf(v.y - __uint_as_float(h1)));
            *(uint4*)&ksu[row * 264 + kq * 8 + 4] =
                make_uint4(h2, ftf(v.z - __uint_as_float(h2)),
                           h3, ftf(v.w - __uint_as_float(h3)));
            float4 w = *(const float4*)&gb[(size_t)(m0 + row) * CI + kq * 4];
            // addr(m,ci) = (m>>3)*1024 + ci*8 + (m&3)*2 + ((m>>2)&1); ci = kq*4+j
            const int base = (row >> 3) * 1024 + kq * 32 + (row & 3) * 2 + ((row >> 2) & 1);
            vsu[base]      = ftf(w.x);
            vsu[base + 8]  = ftf(w.y);
            vsu[base + 16] = ftf(w.z);
            vsu[base + 24] = ftf(w.w);
        }
        __syncthreads();

        float s[8][4];
#pragma unroll
        for (int j = 0; j < 8; ++j)
#pragma unroll
            for (int qd = 0; qd < 4; ++qd) s[j][qd] = 0.f;
#pragma unroll 4
        for (int kk = 0; kk < 16; ++kk) {
            const int qbase = (wrow + g) * 132 + kk * 8 + t;
            float a0f = qs[qbase];               // Q[g][k]
            float a1f = qs[qbase + 8 * 132];     // Q[g+8][k]
            float a2f = qs[qbase + 4];           // Q[g][k+4]
            float a3f = qs[qbase + 8 * 132 + 4]; // Q[g+8][k+4]
            unsigned ah0 = ftf(a0f), ah1 = ftf(a1f), ah2 = ftf(a2f), ah3 = ftf(a3f);
            unsigned al0 = ftf(a0f - __uint_as_float(ah0));
            unsigned al1 = ftf(a1f - __uint_as_float(ah1));
            unsigned al2 = ftf(a2f - __uint_as_float(ah2));
            unsigned al3 = ftf(a3f - __uint_as_float(ah3));
#pragma unroll
            for (int j = 0; j < 8; ++j) {
                const int kb2 = (8 * j + g) * 264 + 2 * (kk * 8 + t);
                uint2 b0 = *(uint2*)&ksu[kb2];       // K[col][k] (hi,lo)
                uint2 b1 = *(uint2*)&ksu[kb2 + 8];   // K[col][k+4]
                mma8(s[j], ah0, ah1, ah2, ah3, b0.x, b1.x);
                mma8(s[j], ah0, ah1, ah2, ah3, b0.y, b1.y);
                mma8(s[j], al0, al1, al2, al3, b0.x, b1.x);
            }
        }

#pragma unroll
        for (int r = 0; r < 2; ++r) {
            float tm = -1e30f;
#pragma unroll
            for (int j = 0; j < 8; ++j)
                tm = fmaxf(tm, fmaxf(s[j][2 * r], s[j][2 * r + 1]));
            tm = fmaxf(tm, __shfl_xor_sync(0xffffffffu, tm, 1));
            tm = fmaxf(tm, __shfl_xor_sync(0xffffffffu, tm, 2));
            const float mnew = fmaxf(mr[r], tm);
            const float scale = __expf(mr[r] - mnew);
            float sum = 0.f;
#pragma unroll
            for (int j = 0; j < 8; ++j) {
                float e0 = __expf(s[j][2 * r] - mnew);
                float e1 = __expf(s[j][2 * r + 1] - mnew);
                s[j][2 * r] = e0; s[j][2 * r + 1] = e1;
                sum += e0 + e1;
            }
            sum += __shfl_xor_sync(0xffffffffu, sum, 1);
            sum += __shfl_xor_sync(0xffffffffu, sum, 2);
            lr[r] = lr[r] * scale + sum;
            mr[r] = mnew;
#pragma unroll
            for (int jt = 0; jt < 16; ++jt) {
                o[jt][2 * r] *= scale; o[jt][2 * r + 1] *= scale;
            }
            const int prow = wrow + g + 8 * r;
#pragma unroll
            for (int j = 0; j < 8; ++j)
                *(uint2*)&psu[prow * 68 + 8 * j + 2 * t] =
                    make_uint2(ftf(s[j][2 * r]), ftf(s[j][2 * r + 1]));
        }
        __syncwarp();

#pragma unroll 2
        for (int kk = 0; kk < 8; ++kk) {
            const int pb = (wrow + g) * 68 + kk * 8 + t;
            unsigned a0 = psu[pb];                // P[g][k]
            unsigned a1 = psu[pb + 8 * 68];       // P[g+8][k]
            unsigned a2 = psu[pb + 4];            // P[g][k+4]
            unsigned a3 = psu[pb + 8 * 68 + 4];   // P[g+8][k+4]
#pragma unroll
            for (int j = 0; j < 16; ++j) {
                // uint2 gives V[ci][m=k+t] and V[ci][m=k+t+4] via interleaving
                uint2 bp = *(uint2*)&vsu[kk * 1024 + (8 * j + g) * 8 + t * 2];
                mma8(o[j], a0, a1, a2, a3, bp.x, bp.y);
            }
        }
    }

    const float inv0 = 1.f / lr[0], inv1 = 1.f / lr[1];
    float* yb = y + (size_t)b * HWN * CI;
#pragma unroll
    for (int j = 0; j < 16; ++j) {
        const int col = 8 * j + 2 * t;
        *(float2*)&yb[(size_t)(n0 + wrow + g) * CI + col] =
            make_float2(o[j][0] * inv0, o[j][1] * inv0);
        *(float2*)&yb[(size_t)(n0 + wrow + g + 8) * CI + col] =
            make_float2(o[j][2] * inv1, o[j][3] * inv1);
    }
}

// ---- BN stats: fp32 partials per 256-row stripe, then double reduce ----
__global__ __launch_bounds__(256) void bnpart_k(const float* __restrict__ wy) {
    const int p = blockIdx.x, t = threadIdx.x;
    const float* base = wy + (size_t)p * 256 * CC + t;
    float s = 0.f, s2 = 0.f;
#pragma unroll 4
    for (int r = 0; r < 256; ++r) {
        float v = base[(size_t)r * CC];
        s += v; s2 += v * v;
    }
    d_part[0][p][t] = s;
    d_part[1][p][t] = s2;
}

__global__ __launch_bounds__(256) void bnred_k(const float* __restrict__ inp0,
                                               float* __restrict__ out, int off) {
    const int t = threadIdx.x;
    double s = 0.0, s2 = 0.0;
    for (int p = 0; p < 256; ++p) {
        s += (double)d_part[0][p][t];
        s2 += (double)d_part[1][p][t];
    }
    const double cnt = (double)(BB * HWN);
    const double mean = s / cnt;
    const double var = s2 / cnt - mean * mean;
    d_mean[t] = (float)mean;
    d_rstd[t] = (float)rsqrt(var + 1e-5);
    if (t == 0 && off == 1) out[0] = inp0[0];
}

// ---- BN apply + residual + transpose back to [b][co][n] ----
__global__ __launch_bounds__(256) void finalT_k(const float* __restrict__ wy,
                                                const float* __restrict__ x,
                                                const float* __restrict__ gamma,
                                                const float* __restrict__ beta,
                                                float* __restrict__ out, int off) {
    __shared__ float tl[32][33];
    const int b = blockIdx.z, co0 = blockIdx.y * 32, n0 = blockIdx.x * 32;
    const int tx = threadIdx.x, ty = threadIdx.y;
    const float* wb = wy + (size_t)b * HWN * CC;
#pragma unroll
    for (int i = 0; i < 4; ++i)
        tl[ty + 8 * i][tx] = wb[(size_t)(n0 + ty + 8 * i) * CC + co0 + tx];
    __syncthreads();
#pragma unroll
    for (int i = 0; i < 4; ++i) {
        const int co = co0 + ty + 8 * i;
        const float a = d_rstd[co] * gamma[co];
        const float bb2 = beta[co] - d_mean[co] * a;
        const size_t idx = (size_t)b * CC * HWN + (size_t)co * HWN + n0 + tx;
        out[off + idx] = tl[tx][ty + 8 * i] * a + bb2 + x[idx];
    }
}

extern "C" void kernel_launch(void* const* d_in, const int* in_sizes, int n_in,
                              void* d_out, int out_size) {
    const float* inp0 = (const float*)d_in[0];
    const float* x    = (const float*)d_in[1];
    const float* g_w  = (const float*)d_in[2];
    const float* g_b  = (const float*)d_in[3];
    const float* th_w = (const float*)d_in[4];
    const float* th_b = (const float*)d_in[5];
    const float* ph_w = (const float*)d_in[6];
    const float* ph_b = (const float*)d_in[7];
    const float* W_w  = (const float*)d_in[8];
    const float* W_b  = (const float*)d_in[9];
    const float* gam  = (const float*)d_in[10];
    const float* bet  = (const float*)d_in[11];
    float* out = (float*)d_out;

    float *p_xt, *p_theta, *p_gf, *p_pf, *p_gp, *p_pp, *p_yy, *p_wy;
    cudaGetSymbolAddress((void**)&p_xt, d_xt);
    cudaGetSymbolAddress((void**)&p_theta, d_theta);
    cudaGetSymbolAddress((void**)&p_gf, d_gf);
    cudaGetSymbolAddress((void**)&p_pf, d_pf);
    cudaGetSymbolAddress((void**)&p_gp, d_gp);
    cudaGetSymbolAddress((void**)&p_pp, d_pp);
    cudaGetSymbolAddress((void**)&p_yy, d_yy);
    cudaGetSymbolAddress((void**)&p_wy, d_wy);

    const int GEMM_P_SMEM = 2 * 128 * 68 * 4;                            // 69632
    const int GEMM_SMEM   = 2 * 128 * 36 * 4;                            // 36864
    const int ATTN_SMEM = (128 * 132 + 64 * 264 + 8192 + 128 * 68) * 4;  // 202752
    cudaFuncSetAttribute(gemm_k<256, true>,  cudaFuncAttributeMaxDynamicSharedMemorySize, GEMM_P_SMEM);
    cudaFuncSetAttribute(gemm_k<128, true>,  cudaFuncAttributeMaxDynamicSharedMemorySize, GEMM_P_SMEM);
    cudaFuncSetAttribute(gemm_k<256, false>, cudaFuncAttributeMaxDynamicSharedMemorySize, GEMM_SMEM);
    cudaFuncSetAttribute(attn_k, cudaFuncAttributeMaxDynamicSharedMemorySize, ATTN_SMEM);

    transpose_k<<<dim3(HWN / 32, CC / 32, BB), dim3(32, 8)>>>(x, p_xt);

    gemm_k<256, true><<<dim3(32, 1, BB), 256, GEMM_P_SMEM>>>(
        p_xt, (long)HWN * CC, th_w, th_b, p_theta, CI, (long)HWN * CI);
    gemm_k<256, true><<<dim3(32, 1, BB), 256, GEMM_P_SMEM>>>(
        p_xt, (long)HWN * CC, ph_w, ph_b, p_pf, CI, (long)HWN * CI);
    gemm_k<256, false><<<dim3(32, 1, BB), 256, GEMM_SMEM>>>(
        p_xt, (long)HWN * CC, g_w, g_b, p_gf, CI, (long)HWN * CI);

    pool_k<<<(BB * NP * 32) / 256, 256>>>(p_gf, p_gp);
    pool_k<<<(BB * NP * 32) / 256, 256>>>(p_pf, p_pp);

    attn_k<<<dim3(HWN / 128, BB), 256, ATTN_SMEM>>>(p_theta, p_pp, p_gp, p_yy);

    gemm_k<128, true><<<dim3(32, 2, BB), 256, GEMM_P_SMEM>>>(
        p_yy, (long)HWN * CI, W_w, W_b, p_wy, CC, (long)HWN * CC);

    bnpart_k<<<256, 256>>>(p_wy);

    const int total = BB * CC * HWN;
    const int off = (out_size > total) ? (out_size - total) : 0;
    bnred_k<<<1, 256>>>(inp0, out, off);

    finalT_k<<<dim3(HWN / 32, CC / 32, BB), dim3(32, 8)>>>(p_wy, x, gam, bet, out, off);
}

// round 6
// speedup vs baseline: 2.2941x; 1.2572x over previous
#include <cuda_runtime.h>
#include <cuda_bf16.h>
#include <math.h>

#define BB   16
#define CC   256
#define CI   128
#define HWN  4096
#define NP   1024

__device__ float d_xt[BB * HWN * CC];      // x transposed [b][n][c]
__device__ float d_theta[BB * HWN * CI];
__device__ float d_gf[BB * HWN * CI];
__device__ float d_pf[BB * HWN * CI];
__device__ float d_gp[BB * NP * CI];
__device__ float d_pp[BB * NP * CI];
__device__ float d_yy[BB * HWN * CI];
__device__ float d_wy[BB * HWN * CC];      // channel-last [b][n][co]
__device__ float d_part[2][256][256];
__device__ float d_mean[CC];
__device__ float d_rstd[CC];

__device__ __forceinline__ unsigned ftf(float x) {
    unsigned u; asm("cvt.rna.tf32.f32 %0,%1;" : "=r"(u) : "f"(x)); return u;
}
// tf32 m16n8k8 fragments (PTX ISA): a0=A[g][t] a1=A[g+8][t] a2=A[g][t+4] a3=A[g+8][t+4]
//   b0=B[n][t] b1=B[n][t+4]; c = (g,2t),(g,2t+1),(g+8,2t),(g+8,2t+1)
__device__ __forceinline__ void mma8(float* c, unsigned a0, unsigned a1, unsigned a2, unsigned a3,
                                     unsigned b0, unsigned b1) {
    asm volatile("mma.sync.aligned.m16n8k8.row.col.f32.tf32.tf32.f32 "
                 "{%0,%1,%2,%3},{%4,%5,%6,%7},{%8,%9},{%0,%1,%2,%3};"
                 : "+f"(c[0]), "+f"(c[1]), "+f"(c[2]), "+f"(c[3])
                 : "r"(a0), "r"(a1), "r"(a2), "r"(a3), "r"(b0), "r"(b1));
}
// bf16 m16n8k16 fragments (PTX ISA), each b32 = 2 bf16 (low = even k):
//   a0=A[g][2t,2t+1] a1=A[g+8][2t,2t+1] a2=A[g][2t+8,2t+9] a3=A[g+8][2t+8,2t+9]
//   b0=B[n][2t,2t+1] b1=B[n][2t+8,2t+9]; c layout same as mma8
__device__ __forceinline__ void mma16(float* c, unsigned a0, unsigned a1, unsigned a2, unsigned a3,
                                      unsigned b0, unsigned b1) {
    asm volatile("mma.sync.aligned.m16n8k16.row.col.f32.bf16.bf16.f32 "
                 "{%0,%1,%2,%3},{%4,%5,%6,%7},{%8,%9},{%0,%1,%2,%3};"
                 : "+f"(c[0]), "+f"(c[1]), "+f"(c[2]), "+f"(c[3])
                 : "r"(a0), "r"(a1), "r"(a2), "r"(a3), "r"(b0), "r"(b1));
}
// split (a,b) into packed bf16x2 hi and lo (low half = a)
__device__ __forceinline__ void split_pair(float a, float b, unsigned &hi, unsigned &lo) {
    __nv_bfloat16 ha = __float2bfloat16_rn(a), hb = __float2bfloat16_rn(b);
    float ra = a - __bfloat162float(ha), rb = b - __bfloat162float(hb);
    __nv_bfloat162 hv; hv.x = ha; hv.y = hb;
    __nv_bfloat162 lv; lv.x = __float2bfloat16_rn(ra); lv.y = __float2bfloat16_rn(rb);
    hi = *(unsigned*)&hv; lo = *(unsigned*)&lv;
}

// ---- x[b][c][n] -> xt[b][n][c] ----
__global__ __launch_bounds__(256) void transpose_k(const float* __restrict__ x,
                                                   float* __restrict__ xt) {
    __shared__ float tl[32][33];
    const int b = blockIdx.z, c0 = blockIdx.y * 32, n0 = blockIdx.x * 32;
    const int tx = threadIdx.x, ty = threadIdx.y;
    const float* xb = x + (size_t)b * CC * HWN;
    float* xo = xt + (size_t)b * HWN * CC;
#pragma unroll
    for (int i = 0; i < 4; ++i)
        tl[ty + 8 * i][tx] = xb[(size_t)(c0 + ty + 8 * i) * HWN + n0 + tx];
    __syncthreads();
#pragma unroll
    for (int i = 0; i < 4; ++i)
        xo[(size_t)(n0 + ty + 8 * i) * CC + c0 + tx] = tl[tx][ty + 8 * i];
}

// ---- GEMM: C[row][col] = A[row][:K].B[col][:K] + bias[col]; tile 128x128, 8 warps ----
// PRECISE: 3-term split-bf16 (hh, hl, lh) via m16n8k16. else plain tf32 m16n8k8.
template<int K, bool PRECISE>
__global__ __launch_bounds__(256) void gemm_k(const float* __restrict__ A, long aStride,
                                              const float* __restrict__ B,
                                              const float* __restrict__ bias,
                                              float* __restrict__ C, int ldc, long cStride) {
    extern __shared__ float smc[];
    const int LD = 36;     // 32 words per 32-k chunk (+4 pad) for both variants
    unsigned* Asu = (unsigned*)smc;
    unsigned* Bsu = Asu + 128 * LD;
    const int b = blockIdx.z;
    const int row0 = blockIdx.x * 128, col0 = blockIdx.y * 128;
    const int tid = threadIdx.x, lane = tid & 31, wid = tid >> 5;
    const int g = lane >> 2, t = lane & 3;
    const int wm = (wid & 3) * 32, wn = (wid >> 2) * 64;
    const float* Ab = A + (size_t)b * aStride;
    float* Cb = C + (size_t)b * cStride;

    float acc[2][8][4];
#pragma unroll
    for (int mt = 0; mt < 2; ++mt)
#pragma unroll
        for (int j = 0; j < 8; ++j)
#pragma unroll
            for (int q = 0; q < 4; ++q) acc[mt][j][q] = 0.f;

    for (int c0 = 0; c0 < K; c0 += 32) {
        __syncthreads();
#pragma unroll
        for (int i = 0; i < 4; ++i) {
            const int id = tid + i * 256;
            const int row = id >> 3, kq = id & 7;
            float4 va = *(const float4*)&Ab[(size_t)(row0 + row) * K + c0 + kq * 4];
            float4 vb = *(const float4*)&B[(size_t)(col0 + row) * K + c0 + kq * 4];
            if (PRECISE) {
                // word layout per row: pair p at offsets 2p (hi), 2p+1 (lo)
                unsigned h0, l0, h1, l1;
                split_pair(va.x, va.y, h0, l0);
                split_pair(va.z, va.w, h1, l1);
                *(uint4*)&Asu[row * 36 + kq * 4] = make_uint4(h0, l0, h1, l1);
                split_pair(vb.x, vb.y, h0, l0);
                split_pair(vb.z, vb.w, h1, l1);
                *(uint4*)&Bsu[row * 36 + kq * 4] = make_uint4(h0, l0, h1, l1);
            } else {
                *(uint4*)&Asu[row * 36 + kq * 4] =
                    make_uint4(ftf(va.x), ftf(va.y), ftf(va.z), ftf(va.w));
                *(uint4*)&Bsu[row * 36 + kq * 4] =
                    make_uint4(ftf(vb.x), ftf(vb.y), ftf(vb.z), ftf(vb.w));
            }
        }
        __syncthreads();
        if (PRECISE) {
            // two k16 steps per 32-k chunk
#pragma unroll
            for (int kk = 0; kk < 2; ++kk) {
                unsigned ah[2][4], al[2][4];
#pragma unroll
                for (int mt = 0; mt < 2; ++mt) {
                    const int rb = (wm + mt * 16 + g) * 36 + kk * 16 + 2 * t;
                    uint2 p0 = *(uint2*)&Asu[rb];               // A[g][2t..] (hi,lo)
                    uint2 p1 = *(uint2*)&Asu[rb + 8 * 36];      // A[g+8][2t..]
                    uint2 p2 = *(uint2*)&Asu[rb + 8];           // A[g][2t+8..]
                    uint2 p3 = *(uint2*)&Asu[rb + 8 * 36 + 8];  // A[g+8][2t+8..]
                    ah[mt][0] = p0.x; al[mt][0] = p0.y;
                    ah[mt][1] = p1.x; al[mt][1] = p1.y;
                    ah[mt][2] = p2.x; al[mt][2] = p2.y;
                    ah[mt][3] = p3.x; al[mt][3] = p3.y;
                }
#pragma unroll
                for (int j = 0; j < 8; ++j) {
                    const int nb = (wn + 8 * j + g) * 36 + kk * 16 + 2 * t;
                    uint2 q0 = *(uint2*)&Bsu[nb];       // B[col][2t..] (hi,lo)
                    uint2 q1 = *(uint2*)&Bsu[nb + 8];   // B[col][2t+8..]
#pragma unroll
                    for (int mt = 0; mt < 2; ++mt) {
                        mma16(acc[mt][j], ah[mt][0], ah[mt][1], ah[mt][2], ah[mt][3], q0.x, q1.x);
                        mma16(acc[mt][j], ah[mt][0], ah[mt][1], ah[mt][2], ah[mt][3], q0.y, q1.y);
                        mma16(acc[mt][j], al[mt][0], al[mt][1], al[mt][2], al[mt][3], q0.x, q1.x);
                    }
                }
            }
        } else {
#pragma unroll
            for (int kk = 0; kk < 4; ++kk) {
                unsigned a[2][4];
#pragma unroll
                for (int mt = 0; mt < 2; ++mt) {
                    const int rb = (wm + mt * 16 + g) * 36 + kk * 8 + t;
                    a[mt][0] = Asu[rb];                 // A[g][k]
                    a[mt][1] = Asu[rb + 8 * 36];        // A[g+8][k]
                    a[mt][2] = Asu[rb + 4];             // A[g][k+4]
                    a[mt][3] = Asu[rb + 8 * 36 + 4];    // A[g+8][k+4]
                }
#pragma unroll
                for (int j = 0; j < 8; ++j) {
                    const int nb = (wn + 8 * j + g) * 36 + kk * 8 + t;
                    unsigned b0 = Bsu[nb], b1 = Bsu[nb + 4];
#pragma unroll
                    for (int mt = 0; mt < 2; ++mt)
                        mma8(acc[mt][j], a[mt][0], a[mt][1], a[mt][2], a[mt][3], b0, b1);
                }
            }
        }
    }
#pragma unroll
    for (int mt = 0; mt < 2; ++mt)
#pragma unroll
        for (int j = 0; j < 8; ++j) {
            const int col = col0 + wn + 8 * j + 2 * t;
            float2 bv = *(const float2*)&bias[col];
            const int r = row0 + wm + mt * 16 + g;
            *(float2*)&Cb[(size_t)r * ldc + col] =
                make_float2(acc[mt][j][0] + bv.x, acc[mt][j][1] + bv.y);
            *(float2*)&Cb[(size_t)(r + 8) * ldc + col] =
                make_float2(acc[mt][j][2] + bv.x, acc[mt][j][3] + bv.y);
        }
}

// ---- 2x2 maxpool, channel-last ----
__global__ __launch_bounds__(256) void pool_k(const float* __restrict__ in,
                                              float* __restrict__ out) {
    const int gi = blockIdx.x * 256 + threadIdx.x;
    const int b = gi / (NP * 32);
    const int rem = gi - b * (NP * 32);
    const int m = rem >> 5, k4 = rem & 31;
    const int ph = m >> 5, pw = m & 31;
    const int n00 = ph * 128 + pw * 2;
    const float* ib = in + (size_t)b * HWN * CI + (size_t)n00 * CI + k4 * 4;
    float4 v0 = *(const float4*)ib;
    float4 v1 = *(const float4*)(ib + CI);
    float4 v2 = *(const float4*)(ib + 64 * CI);
    float4 v3 = *(const float4*)(ib + 65 * CI);
    float4 r;
    r.x = fmaxf(fmaxf(v0.x, v1.x), fmaxf(v2.x, v3.x));
    r.y = fmaxf(fmaxf(v0.y, v1.y), fmaxf(v2.y, v3.y));
    r.z = fmaxf(fmaxf(v0.z, v1.z), fmaxf(v2.z, v3.z));
    r.w = fmaxf(fmaxf(v0.w, v1.w), fmaxf(v2.w, v3.w));
    *(float4*)&out[(size_t)b * NP * CI + (size_t)m * CI + k4 * 4] = r;
}

// ---- fused attention: QK split-bf16 (3-term m16n8k16), PV plain tf32 m16n8k8 ----
__global__ __launch_bounds__(256) void attn_k(const float* __restrict__ q,
                                              const float* __restrict__ kp,
                                              const float* __restrict__ gp,
                                              float* __restrict__ y) {
    extern __shared__ float sm[];
    unsigned* qsu = (unsigned*)sm;       // 128 x 132 (hi/lo bf16x2 pairs)
    unsigned* ksu = qsu + 128 * 132;     // 64 x 132
    unsigned* vsu = ksu + 64 * 132;      // 8192 tf32 interleaved
    unsigned* psu = vsu + 8192;          // 128 x 68 tf32
    const int b = blockIdx.y, n0 = blockIdx.x * 128;
    const int tid = threadIdx.x, lane = tid & 31, wid = tid >> 5;
    const int g = lane >> 2, t = lane & 3;
    const int wrow = wid * 16;
    const float* qb = q  + (size_t)b * HWN * CI;
    const float* kb = kp + (size_t)b * NP * CI;
    const float* gb = gp + (size_t)b * NP * CI;

    // stage Q once, pre-split to bf16 hi/lo
#pragma unroll
    for (int i = 0; i < 16; ++i) {
        const int id = tid + i * 256;
        const int row = id >> 5, k4 = id & 31;
        float4 v = *(const float4*)&qb[(size_t)(n0 + row) * CI + k4 * 4];
        unsigned h0, l0, h1, l1;
        split_pair(v.x, v.y, h0, l0);
        split_pair(v.z, v.w, h1, l1);
        *(uint4*)&qsu[row * 132 + k4 * 4] = make_uint4(h0, l0, h1, l1);
    }

    float o[16][4];
#pragma unroll
    for (int j = 0; j < 16; ++j)
#pragma unroll
        for (int qd = 0; qd < 4; ++qd) o[j][qd] = 0.f;
    float mr[2] = {-1e30f, -1e30f}, lr[2] = {0.f, 0.f};

    for (int iter = 0; iter < 16; ++iter) {
        const int m0 = iter * 64;
        __syncthreads();
        // stage K (split bf16) + V (tf32 interleaved): 64 rows x 32 float4
#pragma unroll
        for (int i = 0; i < 8; ++i) {
            const int id = tid + i * 256;
            const int row = id >> 5, kq = id & 31;
            float4 v = *(const float4*)&kb[(size_t)(m0 + row) * CI + kq * 4];
            unsigned h0, l0, h1, l1;
            split_pair(v.x, v.y, h0, l0);
            split_pair(v.z, v.w, h1, l1);
            *(uint4*)&ksu[row * 132 + kq * 4] = make_uint4(h0, l0, h1, l1);
            float4 w = *(const float4*)&gb[(size_t)(m0 + row) * CI + kq * 4];
            // addr(m,ci) = (m>>3)*1024 + ci*8 + (m&3)*2 + ((m>>2)&1)
            const int base = (row >> 3) * 1024 + kq * 32 + (row & 3) * 2 + ((row >> 2) & 1);
            vsu[base]      = ftf(w.x);
            vsu[base + 8]  = ftf(w.y);
            vsu[base + 16] = ftf(w.z);
            vsu[base + 24] = ftf(w.w);
        }
        __syncthreads();

        // S = Q K^T : 8 k16 steps
        float s[8][4];
#pragma unroll
        for (int j = 0; j < 8; ++j)
#pragma unroll
            for (int qd = 0; qd < 4; ++qd) s[j][qd] = 0.f;
#pragma unroll 4
        for (int kk = 0; kk < 8; ++kk) {
            const int qb2 = (wrow + g) * 132 + kk * 16 + 2 * t;
            uint2 p0 = *(uint2*)&qsu[qb2];               // Q[g][2t..]
            uint2 p1 = *(uint2*)&qsu[qb2 + 8 * 132];     // Q[g+8][2t..]
            uint2 p2 = *(uint2*)&qsu[qb2 + 8];           // Q[g][2t+8..]
            uint2 p3 = *(uint2*)&qsu[qb2 + 8 * 132 + 8]; // Q[g+8][2t+8..]
#pragma unroll
            for (int j = 0; j < 8; ++j) {
                const int kb2 = (8 * j + g) * 132 + kk * 16 + 2 * t;
                uint2 q0 = *(uint2*)&ksu[kb2];
                uint2 q1 = *(uint2*)&ksu[kb2 + 8];
                mma16(s[j], p0.x, p1.x, p2.x, p3.x, q0.x, q1.x);
                mma16(s[j], p0.x, p1.x, p2.x, p3.x, q0.y, q1.y);
                mma16(s[j], p0.y, p1.y, p2.y, p3.y, q0.x, q1.x);
            }
        }

#pragma unroll
        for (int r = 0; r < 2; ++r) {
            float tm = -1e30f;
#pragma unroll
            for (int j = 0; j < 8; ++j)
                tm = fmaxf(tm, fmaxf(s[j][2 * r], s[j][2 * r + 1]));
            tm = fmaxf(tm, __shfl_xor_sync(0xffffffffu, tm, 1));
            tm = fmaxf(tm, __shfl_xor_sync(0xffffffffu, tm, 2));
            const float mnew = fmaxf(mr[r], tm);
            const float scale = __expf(mr[r] - mnew);
            float sum = 0.f;
#pragma unroll
            for (int j = 0; j < 8; ++j) {
                float e0 = __expf(s[j][2 * r] - mnew);
                float e1 = __expf(s[j][2 * r + 1] - mnew);
                s[j][2 * r] = e0; s[j][2 * r + 1] = e1;
                sum += e0 + e1;
            }
            sum += __shfl_xor_sync(0xffffffffu, sum, 1);
            sum += __shfl_xor_sync(0xffffffffu, sum, 2);
            lr[r] = lr[r] * scale + sum;
            mr[r] = mnew;
#pragma unroll
            for (int jt = 0; jt < 16; ++jt) {
                o[jt][2 * r] *= scale; o[jt][2 * r + 1] *= scale;
            }
            const int prow = wrow + g + 8 * r;
#pragma unroll
            for (int j = 0; j < 8; ++j)
                *(uint2*)&psu[prow * 68 + 8 * j + 2 * t] =
                    make_uint2(ftf(s[j][2 * r]), ftf(s[j][2 * r + 1]));
        }
        __syncwarp();

        // O += P V (plain tf32 m16n8k8)
#pragma unroll 2
        for (int kk = 0; kk < 8; ++kk) {
            const int pb = (wrow + g) * 68 + kk * 8 + t;
            unsigned a0 = psu[pb];                // P[g][k]
            unsigned a1 = psu[pb + 8 * 68];       // P[g+8][k]
            unsigned a2 = psu[pb + 4];            // P[g][k+4]
            unsigned a3 = psu[pb + 8 * 68 + 4];   // P[g+8][k+4]
#pragma unroll
            for (int j = 0; j < 16; ++j) {
                uint2 bp = *(uint2*)&vsu[kk * 1024 + (8 * j + g) * 8 + t * 2];
                mma8(o[j], a0, a1, a2, a3, bp.x, bp.y);
            }
        }
    }

    const float inv0 = 1.f / lr[0], inv1 = 1.f / lr[1];
    float* yb = y + (size_t)b * HWN * CI;
#pragma unroll
    for (int j = 0; j < 16; ++j) {
        const int col = 8 * j + 2 * t;
        *(float2*)&yb[(size_t)(n0 + wrow + g) * CI + col] =
            make_float2(o[j][0] * inv0, o[j][1] * inv0);
        *(float2*)&yb[(size_t)(n0 + wrow + g + 8) * CI + col] =
            make_float2(o[j][2] * inv1, o[j][3] * inv1);
    }
}

// ---- BN stats: fp32 partials per 256-row stripe, then double reduce ----
__global__ __launch_bounds__(256) void bnpart_k(const float* __restrict__ wy) {
    const int p = blockIdx.x, t = threadIdx.x;
    const float* base = wy + (size_t)p * 256 * CC + t;
    float s = 0.f, s2 = 0.f;
#pragma unroll 4
    for (int r = 0; r < 256; ++r) {
        float v = base[(size_t)r * CC];
        s += v; s2 += v * v;
    }
    d_part[0][p][t] = s;
    d_part[1][p][t] = s2;
}

__global__ __launch_bounds__(256) void bnred_k(const float* __restrict__ inp0,
                                               float* __restrict__ out, int off) {
    const int t = threadIdx.x;
    double s = 0.0, s2 = 0.0;
    for (int p = 0; p < 256; ++p) {
        s += (double)d_part[0][p][t];
        s2 += (double)d_part[1][p][t];
    }
    const double cnt = (double)(BB * HWN);
    const double mean = s / cnt;
    const double var = s2 / cnt - mean * mean;
    d_mean[t] = (float)mean;
    d_rstd[t] = (float)rsqrt(var + 1e-5);
    if (t == 0 && off == 1) out[0] = inp0[0];
}

// ---- BN apply + residual + transpose back to [b][co][n] ----
__global__ __launch_bounds__(256) void finalT_k(const float* __restrict__ wy,
                                                const float* __restrict__ x,
                                                const float* __restrict__ gamma,
                                                const float* __restrict__ beta,
                                                float* __restrict__ out, int off) {
    __shared__ float tl[32][33];
    const int b = blockIdx.z, co0 = blockIdx.y * 32, n0 = blockIdx.x * 32;
    const int tx = threadIdx.x, ty = threadIdx.y;
    const float* wb = wy + (size_t)b * HWN * CC;
#pragma unroll
    for (int i = 0; i < 4; ++i)
        tl[ty + 8 * i][tx] = wb[(size_t)(n0 + ty + 8 * i) * CC + co0 + tx];
    __syncthreads();
#pragma unroll
    for (int i = 0; i < 4; ++i) {
        const int co = co0 + ty + 8 * i;
        const float a = d_rstd[co] * gamma[co];
        const float bb2 = beta[co] - d_mean[co] * a;
        const size_t idx = (size_t)b * CC * HWN + (size_t)co * HWN + n0 + tx;
        out[off + idx] = tl[tx][ty + 8 * i] * a + bb2 + x[idx];
    }
}

extern "C" void kernel_launch(void* const* d_in, const int* in_sizes, int n_in,
                              void* d_out, int out_size) {
    const float* inp0 = (const float*)d_in[0];
    const float* x    = (const float*)d_in[1];
    const float* g_w  = (const float*)d_in[2];
    const float* g_b  = (const float*)d_in[3];
    const float* th_w = (const float*)d_in[4];
    const float* th_b = (const float*)d_in[5];
    const float* ph_w = (const float*)d_in[6];
    const float* ph_b = (const float*)d_in[7];
    const float* W_w  = (const float*)d_in[8];
    const float* W_b  = (const float*)d_in[9];
    const float* gam  = (const float*)d_in[10];
    const float* bet  = (const float*)d_in[11];
    float* out = (float*)d_out;

    float *p_xt, *p_theta, *p_gf, *p_pf, *p_gp, *p_pp, *p_yy, *p_wy;
    cudaGetSymbolAddress((void**)&p_xt, d_xt);
    cudaGetSymbolAddress((void**)&p_theta, d_theta);
    cudaGetSymbolAddress((void**)&p_gf, d_gf);
    cudaGetSymbolAddress((void**)&p_pf, d_pf);
    cudaGetSymbolAddress((void**)&p_gp, d_gp);
    cudaGetSymbolAddress((void**)&p_pp, d_pp);
    cudaGetSymbolAddress((void**)&p_yy, d_yy);
    cudaGetSymbolAddress((void**)&p_wy, d_wy);

    const int GEMM_SMEM = 2 * 128 * 36 * 4;                              // 36864
    const int ATTN_SMEM = (128 * 132 + 64 * 132 + 8192 + 128 * 68) * 4;  // 168960
    cudaFuncSetAttribute(gemm_k<256, true>,  cudaFuncAttributeMaxDynamicSharedMemorySize, GEMM_SMEM);
    cudaFuncSetAttribute(gemm_k<128, true>,  cudaFuncAttributeMaxDynamicSharedMemorySize, GEMM_SMEM);
    cudaFuncSetAttribute(gemm_k<256, false>, cudaFuncAttributeMaxDynamicSharedMemorySize, GEMM_SMEM);
    cudaFuncSetAttribute(attn_k, cudaFuncAttributeMaxDynamicSharedMemorySize, ATTN_SMEM);

    transpose_k<<<dim3(HWN / 32, CC / 32, BB), dim3(32, 8)>>>(x, p_xt);

    gemm_k<256, true><<<dim3(32, 1, BB), 256, GEMM_SMEM>>>(
        p_xt, (long)HWN * CC, th_w, th_b, p_theta, CI, (long)HWN * CI);
    gemm_k<256, true><<<dim3(32, 1, BB), 256, GEMM_SMEM>>>(
        p_xt, (long)HWN * CC, ph_w, ph_b, p_pf, CI, (long)HWN * CI);
    gemm_k<256, false><<<dim3(32, 1, BB), 256, GEMM_SMEM>>>(
        p_xt, (long)HWN * CC, g_w, g_b, p_gf, CI, (long)HWN * CI);

    pool_k<<<(BB * NP * 32) / 256, 256>>>(p_gf, p_gp);
    pool_k<<<(BB * NP * 32) / 256, 256>>>(p_pf, p_pp);

    attn_k<<<dim3(HWN / 128, BB), 256, ATTN_SMEM>>>(p_theta, p_pp, p_gp, p_yy);

    gemm_k<128, true><<<dim3(32, 2, BB), 256, GEMM_SMEM>>>(
        p_yy, (long)HWN * CI, W_w, W_b, p_wy, CC, (long)HWN * CC);

    bnpart_k<<<256, 256>>>(p_wy);

    const int total = BB * CC * HWN;
    const int off = (out_size > total) ? (out_size - total) : 0;
    bnred_k<<<1, 256>>>(inp0, out, off);

    finalT_k<<<dim3(HWN / 32, CC / 32, BB), dim3(32, 8)>>>(p_wy, x, gam, bet, out, off);
}

// round 7
// speedup vs baseline: 2.9767x; 1.2975x over previous
#include <cuda_runtime.h>
#include <cuda_bf16.h>
#include <math.h>

#define BB   16
#define CC   256
#define CI   128
#define HWN  4096
#define NP   1024

__device__ float d_xt[BB * HWN * CC];      // x transposed [b][n][c]
__device__ float d_theta[BB * HWN * CI];
__device__ float d_gf[BB * HWN * CI];
__device__ float d_pf[BB * HWN * CI];
__device__ unsigned d_kpack[BB * NP * 128];  // phi pooled, split-bf16 packed
__device__ unsigned d_vpack[BB * NP * 128];  // g pooled, tf32 PV-interleaved
__device__ float d_yy[BB * HWN * CI];
__device__ float d_wy[BB * HWN * CC];      // channel-last [b][n][co]
__device__ float d_part[2][256][256];
__device__ float d_mean[CC];
__device__ float d_rstd[CC];

__device__ __forceinline__ unsigned ftf(float x) {
    unsigned u; asm("cvt.rna.tf32.f32 %0,%1;" : "=r"(u) : "f"(x)); return u;
}
// tf32 m16n8k8 fragments (PTX ISA): a0=A[g][t] a1=A[g+8][t] a2=A[g][t+4] a3=A[g+8][t+4]
//   b0=B[n][t] b1=B[n][t+4]; c = (g,2t),(g,2t+1),(g+8,2t),(g+8,2t+1)
__device__ __forceinline__ void mma8(float* c, unsigned a0, unsigned a1, unsigned a2, unsigned a3,
                                     unsigned b0, unsigned b1) {
    asm volatile("mma.sync.aligned.m16n8k8.row.col.f32.tf32.tf32.f32 "
                 "{%0,%1,%2,%3},{%4,%5,%6,%7},{%8,%9},{%0,%1,%2,%3};"
                 : "+f"(c[0]), "+f"(c[1]), "+f"(c[2]), "+f"(c[3])
                 : "r"(a0), "r"(a1), "r"(a2), "r"(a3), "r"(b0), "r"(b1));
}
// bf16 m16n8k16: a0=A[g][2t,2t+1] a1=A[g+8][2t,2t+1] a2=A[g][2t+8,2t+9] a3=A[g+8][2t+8,2t+9]
//   b0=B[n][2t,2t+1] b1=B[n][2t+8,2t+9]; c layout same as mma8
__device__ __forceinline__ void mma16(float* c, unsigned a0, unsigned a1, unsigned a2, unsigned a3,
                                      unsigned b0, unsigned b1) {
    asm volatile("mma.sync.aligned.m16n8k16.row.col.f32.bf16.bf16.f32 "
                 "{%0,%1,%2,%3},{%4,%5,%6,%7},{%8,%9},{%0,%1,%2,%3};"
                 : "+f"(c[0]), "+f"(c[1]), "+f"(c[2]), "+f"(c[3])
                 : "r"(a0), "r"(a1), "r"(a2), "r"(a3), "r"(b0), "r"(b1));
}
__device__ __forceinline__ void split_pair(float a, float b, unsigned &hi, unsigned &lo) {
    __nv_bfloat16 ha = __float2bfloat16_rn(a), hb = __float2bfloat16_rn(b);
    float ra = a - __bfloat162float(ha), rb = b - __bfloat162float(hb);
    __nv_bfloat162 hv; hv.x = ha; hv.y = hb;
    __nv_bfloat162 lv; lv.x = __float2bfloat16_rn(ra); lv.y = __float2bfloat16_rn(rb);
    hi = *(unsigned*)&hv; lo = *(unsigned*)&lv;
}
__device__ __forceinline__ unsigned s2u(const void* p) {
    return (unsigned)__cvta_generic_to_shared(p);
}
__device__ __forceinline__ void cp16(unsigned dst, const void* src) {
    asm volatile("cp.async.cg.shared.global [%0], [%1], 16;" :: "r"(dst), "l"(src) : "memory");
}

// ---- x[b][c][n] -> xt[b][n][c] ----
__global__ __launch_bounds__(256) void transpose_k(const float* __restrict__ x,
                                                   float* __restrict__ xt) {
    __shared__ float tl[32][33];
    const int b = blockIdx.z, c0 = blockIdx.y * 32, n0 = blockIdx.x * 32;
    const int tx = threadIdx.x, ty = threadIdx.y;
    const float* xb = x + (size_t)b * CC * HWN;
    float* xo = xt + (size_t)b * HWN * CC;
#pragma unroll
    for (int i = 0; i < 4; ++i)
        tl[ty + 8 * i][tx] = xb[(size_t)(c0 + ty + 8 * i) * HWN + n0 + tx];
    __syncthreads();
#pragma unroll
    for (int i = 0; i < 4; ++i)
        xo[(size_t)(n0 + ty + 8 * i) * CC + c0 + tx] = tl[tx][ty + 8 * i];
}

// ---- GEMM: C[row][col] = A[row][:K].B[col][:K] + bias[col]; tile 128x128, 8 warps ----
template<int K, bool PRECISE>
__global__ __launch_bounds__(256) void gemm_k(const float* __restrict__ A, long aStride,
                                              const float* __restrict__ B,
                                              const float* __restrict__ bias,
                                              float* __restrict__ C, int ldc, long cStride) {
    extern __shared__ float smc[];
    unsigned* Asu = (unsigned*)smc;
    unsigned* Bsu = Asu + 128 * 36;
    const int b = blockIdx.z;
    const int row0 = blockIdx.x * 128, col0 = blockIdx.y * 128;
    const int tid = threadIdx.x, lane = tid & 31, wid = tid >> 5;
    const int g = lane >> 2, t = lane & 3;
    const int wm = (wid & 3) * 32, wn = (wid >> 2) * 64;
    const float* Ab = A + (size_t)b * aStride;
    float* Cb = C + (size_t)b * cStride;

    float acc[2][8][4];
#pragma unroll
    for (int mt = 0; mt < 2; ++mt)
#pragma unroll
        for (int j = 0; j < 8; ++j)
#pragma unroll
            for (int q = 0; q < 4; ++q) acc[mt][j][q] = 0.f;

    for (int c0 = 0; c0 < K; c0 += 32) {
        __syncthreads();
#pragma unroll
        for (int i = 0; i < 4; ++i) {
            const int id = tid + i * 256;
            const int row = id >> 3, kq = id & 7;
            float4 va = *(const float4*)&Ab[(size_t)(row0 + row) * K + c0 + kq * 4];
            float4 vb = *(const float4*)&B[(size_t)(col0 + row) * K + c0 + kq * 4];
            if (PRECISE) {
                unsigned h0, l0, h1, l1;
                split_pair(va.x, va.y, h0, l0);
                split_pair(va.z, va.w, h1, l1);
                *(uint4*)&Asu[row * 36 + kq * 4] = make_uint4(h0, l0, h1, l1);
                split_pair(vb.x, vb.y, h0, l0);
                split_pair(vb.z, vb.w, h1, l1);
                *(uint4*)&Bsu[row * 36 + kq * 4] = make_uint4(h0, l0, h1, l1);
            } else {
                *(uint4*)&Asu[row * 36 + kq * 4] =
                    make_uint4(ftf(va.x), ftf(va.y), ftf(va.z), ftf(va.w));
                *(uint4*)&Bsu[row * 36 + kq * 4] =
                    make_uint4(ftf(vb.x), ftf(vb.y), ftf(vb.z), ftf(vb.w));
            }
        }
        __syncthreads();
        if (PRECISE) {
#pragma unroll
            for (int kk = 0; kk < 2; ++kk) {
                unsigned ah[2][4], al[2][4];
#pragma unroll
                for (int mt = 0; mt < 2; ++mt) {
                    const int rb = (wm + mt * 16 + g) * 36 + kk * 16 + 2 * t;
                    uint2 p0 = *(uint2*)&Asu[rb];
                    uint2 p1 = *(uint2*)&Asu[rb + 8 * 36];
                    uint2 p2 = *(uint2*)&Asu[rb + 8];
                    uint2 p3 = *(uint2*)&Asu[rb + 8 * 36 + 8];
                    ah[mt][0] = p0.x; al[mt][0] = p0.y;
                    ah[mt][1] = p1.x; al[mt][1] = p1.y;
                    ah[mt][2] = p2.x; al[mt][2] = p2.y;
                    ah[mt][3] = p3.x; al[mt][3] = p3.y;
                }
#pragma unroll
                for (int j = 0; j < 8; ++j) {
                    const int nb = (wn + 8 * j + g) * 36 + kk * 16 + 2 * t;
                    uint2 q0 = *(uint2*)&Bsu[nb];
                    uint2 q1 = *(uint2*)&Bsu[nb + 8];
#pragma unroll
                    for (int mt = 0; mt < 2; ++mt) {
                        mma16(acc[mt][j], ah[mt][0], ah[mt][1], ah[mt][2], ah[mt][3], q0.x, q1.x);
                        mma16(acc[mt][j], ah[mt][0], ah[mt][1], ah[mt][2], ah[mt][3], q0.y, q1.y);
                        mma16(acc[mt][j], al[mt][0], al[mt][1], al[mt][2], al[mt][3], q0.x, q1.x);
                    }
                }
            }
        } else {
#pragma unroll
            for (int kk = 0; kk < 4; ++kk) {
                unsigned a[2][4];
#pragma unroll
                for (int mt = 0; mt < 2; ++mt) {
                    const int rb = (wm + mt * 16 + g) * 36 + kk * 8 + t;
                    a[mt][0] = Asu[rb];
                    a[mt][1] = Asu[rb + 8 * 36];
                    a[mt][2] = Asu[rb + 4];
                    a[mt][3] = Asu[rb + 8 * 36 + 4];
                }
#pragma unroll
                for (int j = 0; j < 8; ++j) {
                    const int nb = (wn + 8 * j + g) * 36 + kk * 8 + t;
                    unsigned b0 = Bsu[nb], b1 = Bsu[nb + 4];
#pragma unroll
                    for (int mt = 0; mt < 2; ++mt)
                        mma8(acc[mt][j], a[mt][0], a[mt][1], a[mt][2], a[mt][3], b0, b1);
                }
            }
        }
    }
#pragma unroll
    for (int mt = 0; mt < 2; ++mt)
#pragma unroll
        for (int j = 0; j < 8; ++j) {
            const int col = col0 + wn + 8 * j + 2 * t;
            float2 bv = *(const float2*)&bias[col];
            const int r = row0 + wm + mt * 16 + g;
            *(float2*)&Cb[(size_t)r * ldc + col] =
                make_float2(acc[mt][j][0] + bv.x, acc[mt][j][1] + bv.y);
            *(float2*)&Cb[(size_t)(r + 8) * ldc + col] =
                make_float2(acc[mt][j][2] + bv.x, acc[mt][j][3] + bv.y);
        }
}

// ---- pool + convert K (phi): split-bf16 packed, word layout matches attn SMEM rows ----
__global__ __launch_bounds__(256) void pool_splitk(const float* __restrict__ in,
                                                   unsigned* __restrict__ out) {
    const int gi = blockIdx.x * 256 + threadIdx.x;
    const int b = gi / (NP * 32);
    const int rem = gi - b * (NP * 32);
    const int m = rem >> 5, kq = rem & 31;
    const int ph = m >> 5, pw = m & 31;
    const int n00 = ph * 128 + pw * 2;
    const float* ib = in + (size_t)b * HWN * CI + (size_t)n00 * CI + kq * 4;
    float4 v0 = *(const float4*)ib;
    float4 v1 = *(const float4*)(ib + CI);
    float4 v2 = *(const float4*)(ib + 64 * CI);
    float4 v3 = *(const float4*)(ib + 65 * CI);
    float4 r;
    r.x = fmaxf(fmaxf(v0.x, v1.x), fmaxf(v2.x, v3.x));
    r.y = fmaxf(fmaxf(v0.y, v1.y), fmaxf(v2.y, v3.y));
    r.z = fmaxf(fmaxf(v0.z, v1.z), fmaxf(v2.z, v3.z));
    r.w = fmaxf(fmaxf(v0.w, v1.w), fmaxf(v2.w, v3.w));
    unsigned h0, l0, h1, l1;
    split_pair(r.x, r.y, h0, l0);
    split_pair(r.z, r.w, h1, l1);
    *(uint4*)&out[((size_t)b * NP + m) * 128 + kq * 4] = make_uint4(h0, l0, h1, l1);
}

// ---- pool + convert V (g): tf32, PV-interleaved, per-64-row-group contiguous ----
__global__ __launch_bounds__(256) void pool_vtf32(const float* __restrict__ in,
                                                  unsigned* __restrict__ out) {
    const int gi = blockIdx.x * 256 + threadIdx.x;
    const int b = gi / (NP * 32);
    const int rem = gi - b * (NP * 32);
    const int m = rem >> 5, kq = rem & 31;
    const int ph = m >> 5, pw = m & 31;
    const int n00 = ph * 128 + pw * 2;
    const float* ib = in + (size_t)b * HWN * CI + (size_t)n00 * CI + kq * 4;
    float4 v0 = *(const float4*)ib;
    float4 v1 = *(const float4*)(ib + CI);
    float4 v2 = *(const float4*)(ib + 64 * CI);
    float4 v3 = *(const float4*)(ib + 65 * CI);
    float4 r;
    r.x = fmaxf(fmaxf(v0.x, v1.x), fmaxf(v2.x, v3.x));
    r.y = fmaxf(fmaxf(v0.y, v1.y), fmaxf(v2.y, v3.y));
    r.z = fmaxf(fmaxf(v0.z, v1.z), fmaxf(v2.z, v3.z));
    r.w = fmaxf(fmaxf(v0.w, v1.w), fmaxf(v2.w, v3.w));
    const int ml = m & 63;
    unsigned* ob = out + (size_t)b * NP * 128 + (size_t)(m >> 6) * 8192;
    const int base = (ml >> 3) * 1024 + kq * 32 + (ml & 3) * 2 + ((ml >> 2) & 1);
    ob[base]      = ftf(r.x);
    ob[base + 8]  = ftf(r.y);
    ob[base + 16] = ftf(r.z);
    ob[base + 24] = ftf(r.w);
}

// ---- fused attention: Q frags in regs, cp.async double-buffered K/V ----
__global__ __launch_bounds__(256) void attn_k(const float* __restrict__ q,
                                              const unsigned* __restrict__ kpk,
                                              const unsigned* __restrict__ vpk,
                                              float* __restrict__ y) {
    extern __shared__ float sm[];
    unsigned* ks  = (unsigned*)sm;       // 2 x 64 x 132
    unsigned* vs  = ks + 2 * 64 * 132;   // 2 x 8192
    unsigned* psu = vs + 2 * 8192;       // 128 x 68
    const int b = blockIdx.y, n0 = blockIdx.x * 128;
    const int tid = threadIdx.x, lane = tid & 31, wid = tid >> 5;
    const int g = lane >> 2, t = lane & 3;
    const int wrow = wid * 16;
    const float* qb = q + (size_t)b * HWN * CI;
    const unsigned* kg = kpk + (size_t)b * NP * 128;
    const unsigned* vg = vpk + (size_t)b * NP * 128;

    // Q fragments in registers: 8 k16 steps x 4 positions, hi+lo
    unsigned qh[8][4], ql[8][4];
    {
        const float* q0p = qb + (size_t)(n0 + wrow + g) * CI;
        const float* q1p = qb + (size_t)(n0 + wrow + g + 8) * CI;
#pragma unroll
        for (int kk = 0; kk < 8; ++kk) {
            float2 v0 = *(const float2*)&q0p[kk * 16 + 2 * t];
            float2 v1 = *(const float2*)&q1p[kk * 16 + 2 * t];
            float2 v2 = *(const float2*)&q0p[kk * 16 + 2 * t + 8];
            float2 v3 = *(const float2*)&q1p[kk * 16 + 2 * t + 8];
            split_pair(v0.x, v0.y, qh[kk][0], ql[kk][0]);
            split_pair(v1.x, v1.y, qh[kk][1], ql[kk][1]);
            split_pair(v2.x, v2.y, qh[kk][2], ql[kk][2]);
            split_pair(v3.x, v3.y, qh[kk][3], ql[kk][3]);
        }
    }

    const unsigned ksBase = s2u(ks), vsBase = s2u(vs);
    // stage tile it into buffer it&1 (16B cp.async chunks)
    auto stage = [&](int it) {
        const unsigned kb = ksBase + (unsigned)((it & 1) * 64 * 132 * 4);
        const unsigned vb = vsBase + (unsigned)((it & 1) * 8192 * 4);
        const unsigned* kgt = kg + (size_t)it * 64 * 128;
        const unsigned* vgt = vg + (size_t)it * 8192;
#pragma unroll
        for (int i = 0; i < 8; ++i) {
            const int id = tid + i * 256;
            const int row = id >> 5, c = id & 31;
            cp16(kb + (unsigned)((row * 132 + c * 4) * 4), kgt + row * 128 + c * 4);
            cp16(vb + (unsigned)(id * 16), vgt + id * 4);
        }
        asm volatile("cp.async.commit_group;" ::: "memory");
    };

    stage(0);

    float o[16][4];
#pragma unroll
    for (int j = 0; j < 16; ++j)
#pragma unroll
        for (int qd = 0; qd < 4; ++qd) o[j][qd] = 0.f;
    float mr[2] = {-1e30f, -1e30f}, lr[2] = {0.f, 0.f};

    for (int iter = 0; iter < 16; ++iter) {
        if (iter < 15) {
            stage(iter + 1);
            asm volatile("cp.async.wait_group 1;" ::: "memory");
        } else {
            asm volatile("cp.async.wait_group 0;" ::: "memory");
        }
        __syncthreads();
        const unsigned* kbuf = ks + (iter & 1) * 64 * 132;
        const unsigned* vbuf = vs + (iter & 1) * 8192;

        // S = Q K^T (3-term split-bf16, m16n8k16)
        float s[8][4];
#pragma unroll
        for (int j = 0; j < 8; ++j)
#pragma unroll
            for (int qd = 0; qd < 4; ++qd) s[j][qd] = 0.f;
#pragma unroll 4
        for (int kk = 0; kk < 8; ++kk) {
#pragma unroll
            for (int j = 0; j < 8; ++j) {
                const int kb2 = (8 * j + g) * 132 + kk * 16 + 2 * t;
                uint2 q0 = *(uint2*)&kbuf[kb2];       // (hi,lo) for k pair 2t
                uint2 q1 = *(uint2*)&kbuf[kb2 + 8];   // (hi,lo) for k pair 2t+8
                mma16(s[j], qh[kk][0], qh[kk][1], qh[kk][2], qh[kk][3], q0.x, q1.x);
                mma16(s[j], qh[kk][0], qh[kk][1], qh[kk][2], qh[kk][3], q0.y, q1.y);
                mma16(s[j], ql[kk][0], ql[kk][1], ql[kk][2], ql[kk][3], q0.x, q1.x);
            }
        }

#pragma unroll
        for (int r = 0; r < 2; ++r) {
            float tm = -1e30f;
#pragma unroll
            for (int j = 0; j < 8; ++j)
                tm = fmaxf(tm, fmaxf(s[j][2 * r], s[j][2 * r + 1]));
            tm = fmaxf(tm, __shfl_xor_sync(0xffffffffu, tm, 1));
            tm = fmaxf(tm, __shfl_xor_sync(0xffffffffu, tm, 2));
            const float mnew = fmaxf(mr[r], tm);
            const float scale = __expf(mr[r] - mnew);
            float sum = 0.f;
#pragma unroll
            for (int j = 0; j < 8; ++j) {
                float e0 = __expf(s[j][2 * r] - mnew);
                float e1 = __expf(s[j][2 * r + 1] - mnew);
                s[j][2 * r] = e0; s[j][2 * r + 1] = e1;
                sum += e0 + e1;
            }
            sum += __shfl_xor_sync(0xffffffffu, sum, 1);
            sum += __shfl_xor_sync(0xffffffffu, sum, 2);
            lr[r] = lr[r] * scale + sum;
            mr[r] = mnew;
#pragma unroll
            for (int jt = 0; jt < 16; ++jt) {
                o[jt][2 * r] *= scale; o[jt][2 * r + 1] *= scale;
            }
            const int prow = wrow + g + 8 * r;
#pragma unroll
            for (int j = 0; j < 8; ++j)
                *(uint2*)&psu[prow * 68 + 8 * j + 2 * t] =
                    make_uint2(ftf(s[j][2 * r]), ftf(s[j][2 * r + 1]));
        }
        __syncwarp();

        // O += P V (plain tf32 m16n8k8)
#pragma unroll 2
        for (int kk = 0; kk < 8; ++kk) {
            const int pb = (wrow + g) * 68 + kk * 8 + t;
            unsigned a0 = psu[pb];
            unsigned a1 = psu[pb + 8 * 68];
            unsigned a2 = psu[pb + 4];
            unsigned a3 = psu[pb + 8 * 68 + 4];
#pragma unroll
            for (int j = 0; j < 16; ++j) {
                uint2 bp = *(uint2*)&vbuf[kk * 1024 + (8 * j + g) * 8 + t * 2];
                mma8(o[j], a0, a1, a2, a3, bp.x, bp.y);
            }
        }
        __syncthreads();   // all reads of this buffer done before it is re-staged
    }

    const float inv0 = 1.f / lr[0], inv1 = 1.f / lr[1];
    float* yb = y + (size_t)b * HWN * CI;
#pragma unroll
    for (int j = 0; j < 16; ++j) {
        const int col = 8 * j + 2 * t;
        *(float2*)&yb[(size_t)(n0 + wrow + g) * CI + col] =
            make_float2(o[j][0] * inv0, o[j][1] * inv0);
        *(float2*)&yb[(size_t)(n0 + wrow + g + 8) * CI + col] =
            make_float2(o[j][2] * inv1, o[j][3] * inv1);
    }
}

// ---- BN stats: fp32 partials per 256-row stripe, then double reduce ----
__global__ __launch_bounds__(256) void bnpart_k(const float* __restrict__ wy) {
    const int p = blockIdx.x, t = threadIdx.x;
    const float* base = wy + (size_t)p * 256 * CC + t;
    float s = 0.f, s2 = 0.f;
#pragma unroll 4
    for (int r = 0; r < 256; ++r) {
        float v = base[(size_t)r * CC];
        s += v; s2 += v * v;
    }
    d_part[0][p][t] = s;
    d_part[1][p][t] = s2;
}

__global__ __launch_bounds__(256) void bnred_k(const float* __restrict__ inp0,
                                               float* __restrict__ out, int off) {
    const int t = threadIdx.x;
    double s = 0.0, s2 = 0.0;
    for (int p = 0; p < 256; ++p) {
        s += (double)d_part[0][p][t];
        s2 += (double)d_part[1][p][t];
    }
    const double cnt = (double)(BB * HWN);
    const double mean = s / cnt;
    const double var = s2 / cnt - mean * mean;
    d_mean[t] = (float)mean;
    d_rstd[t] = (float)rsqrt(var + 1e-5);
    if (t == 0 && off == 1) out[0] = inp0[0];
}

// ---- BN apply + residual + transpose back to [b][co][n] ----
__global__ __launch_bounds__(256) void finalT_k(const float* __restrict__ wy,
                                                const float* __restrict__ x,
                                                const float* __restrict__ gamma,
                                                const float* __restrict__ beta,
                                                float* __restrict__ out, int off) {
    __shared__ float tl[32][33];
    const int b = blockIdx.z, co0 = blockIdx.y * 32, n0 = blockIdx.x * 32;
    const int tx = threadIdx.x, ty = threadIdx.y;
    const float* wb = wy + (size_t)b * HWN * CC;
#pragma unroll
    for (int i = 0; i < 4; ++i)
        tl[ty + 8 * i][tx] = wb[(size_t)(n0 + ty + 8 * i) * CC + co0 + tx];
    __syncthreads();
#pragma unroll
    for (int i = 0; i < 4; ++i) {
        const int co = co0 + ty + 8 * i;
        const float a = d_rstd[co] * gamma[co];
        const float bb2 = beta[co] - d_mean[co] * a;
        const size_t idx = (size_t)b * CC * HWN + (size_t)co * HWN + n0 + tx;
        out[off + idx] = tl[tx][ty + 8 * i] * a + bb2 + x[idx];
    }
}

extern "C" void kernel_launch(void* const* d_in, const int* in_sizes, int n_in,
                              void* d_out, int out_size) {
    const float* inp0 = (const float*)d_in[0];
    const float* x    = (const float*)d_in[1];
    const float* g_w  = (const float*)d_in[2];
    const float* g_b  = (const float*)d_in[3];
    const float* th_w = (const float*)d_in[4];
    const float* th_b = (const float*)d_in[5];
    const float* ph_w = (const float*)d_in[6];
    const float* ph_b = (const float*)d_in[7];
    const float* W_w  = (const float*)d_in[8];
    const float* W_b  = (const float*)d_in[9];
    const float* gam  = (const float*)d_in[10];
    const float* bet  = (const float*)d_in[11];
    float* out = (float*)d_out;

    float *p_xt, *p_theta, *p_gf, *p_pf, *p_yy, *p_wy;
    unsigned *p_kp, *p_vp;
    cudaGetSymbolAddress((void**)&p_xt, d_xt);
    cudaGetSymbolAddress((void**)&p_theta, d_theta);
    cudaGetSymbolAddress((void**)&p_gf, d_gf);
    cudaGetSymbolAddress((void**)&p_pf, d_pf);
    cudaGetSymbolAddress((void**)&p_kp, d_kpack);
    cudaGetSymbolAddress((void**)&p_vp, d_vpack);
    cudaGetSymbolAddress((void**)&p_yy, d_yy);
    cudaGetSymbolAddress((void**)&p_wy, d_wy);

    const int GEMM_SMEM = 2 * 128 * 36 * 4;                      // 36864
    const int ATTN_SMEM = (2 * 64 * 132 + 2 * 8192 + 128 * 68) * 4;  // 167936
    cudaFuncSetAttribute(gemm_k<256, true>,  cudaFuncAttributeMaxDynamicSharedMemorySize, GEMM_SMEM);
    cudaFuncSetAttribute(gemm_k<128, true>,  cudaFuncAttributeMaxDynamicSharedMemorySize, GEMM_SMEM);
    cudaFuncSetAttribute(gemm_k<256, false>, cudaFuncAttributeMaxDynamicSharedMemorySize, GEMM_SMEM);
    cudaFuncSetAttribute(attn_k, cudaFuncAttributeMaxDynamicSharedMemorySize, ATTN_SMEM);

    transpose_k<<<dim3(HWN / 32, CC / 32, BB), dim3(32, 8)>>>(x, p_xt);

    gemm_k<256, true><<<dim3(32, 1, BB), 256, GEMM_SMEM>>>(
        p_xt, (long)HWN * CC, th_w, th_b, p_theta, CI, (long)HWN * CI);
    gemm_k<256, true><<<dim3(32, 1, BB), 256, GEMM_SMEM>>>(
        p_xt, (long)HWN * CC, ph_w, ph_b, p_pf, CI, (long)HWN * CI);
    gemm_k<256, false><<<dim3(32, 1, BB), 256, GEMM_SMEM>>>(
        p_xt, (long)HWN * CC, g_w, g_b, p_gf, CI, (long)HWN * CI);

    pool_splitk<<<(BB * NP * 32) / 256, 256>>>(p_pf, p_kp);
    pool_vtf32<<<(BB * NP * 32) / 256, 256>>>(p_gf, p_vp);

    attn_k<<<dim3(HWN / 128, BB), 256, ATTN_SMEM>>>(p_theta, p_kp, p_vp, p_yy);

    gemm_k<128, true><<<dim3(32, 2, BB), 256, GEMM_SMEM>>>(
        p_yy, (long)HWN * CI, W_w, W_b, p_wy, CC, (long)HWN * CC);

    bnpart_k<<<256, 256>>>(p_wy);

    const int total = BB * CC * HWN;
    const int off = (out_size > total) ? (out_size - total) : 0;
    bnred_k<<<1, 256>>>(inp0, out, off);

    finalT_k<<<dim3(HWN / 32, CC / 32, BB), dim3(32, 8)>>>(p_wy, x, gam, bet, out, off);
}

// round 8
// speedup vs baseline: 3.3594x; 1.1286x over previous
#include <cuda_runtime.h>
#include <cuda_bf16.h>
#include <math.h>

#define BB   16
#define CC   256
#define CI   128
#define HWN  4096
#define NP   1024

__device__ unsigned d_xts[BB * HWN * CC];    // x^T packed split-bf16 (word/elem)
__device__ unsigned d_xtt[BB * HWN * CC];    // x^T tf32
__device__ float    d_theta[BB * HWN * CI];  // theta conv out fp32 (attn Q)
__device__ float    d_gf[BB * HWN * CI];
__device__ float    d_pf[BB * HWN * CI];
__device__ unsigned d_kpack[BB * NP * 128];  // phi pooled, split-bf16 packed
__device__ unsigned d_vpack[BB * NP * 128];  // g pooled, tf32 PV-interleaved
__device__ unsigned d_ypack[BB * HWN * CI];  // attn out, split-bf16 packed
__device__ float    d_wy[BB * HWN * CC];     // W conv out channel-last
__device__ unsigned d_wth[CI * CC];          // packed weights
__device__ unsigned d_wph[CI * CC];
__device__ unsigned d_wg[CI * CC];
__device__ unsigned d_ww[CC * CI];
__device__ float d_part[2][256][256];
__device__ float d_mean[CC];
__device__ float d_rstd[CC];

__device__ __forceinline__ unsigned ftf(float x) {
    unsigned u; asm("cvt.rna.tf32.f32 %0,%1;" : "=r"(u) : "f"(x)); return u;
}
// tf32 m16n8k8: a0=A[g][t] a1=A[g+8][t] a2=A[g][t+4] a3=A[g+8][t+4]; b0=B[n][t] b1=B[n][t+4]
__device__ __forceinline__ void mma8(float* c, unsigned a0, unsigned a1, unsigned a2, unsigned a3,
                                     unsigned b0, unsigned b1) {
    asm volatile("mma.sync.aligned.m16n8k8.row.col.f32.tf32.tf32.f32 "
                 "{%0,%1,%2,%3},{%4,%5,%6,%7},{%8,%9},{%0,%1,%2,%3};"
                 : "+f"(c[0]), "+f"(c[1]), "+f"(c[2]), "+f"(c[3])
                 : "r"(a0), "r"(a1), "r"(a2), "r"(a3), "r"(b0), "r"(b1));
}
// bf16 m16n8k16: a0=A[g][2t,2t+1] a1=A[g+8][..] a2=A[g][2t+8,..] a3=A[g+8][2t+8,..]
__device__ __forceinline__ void mma16(float* c, unsigned a0, unsigned a1, unsigned a2, unsigned a3,
                                      unsigned b0, unsigned b1) {
    asm volatile("mma.sync.aligned.m16n8k16.row.col.f32.bf16.bf16.f32 "
                 "{%0,%1,%2,%3},{%4,%5,%6,%7},{%8,%9},{%0,%1,%2,%3};"
                 : "+f"(c[0]), "+f"(c[1]), "+f"(c[2]), "+f"(c[3])
                 : "r"(a0), "r"(a1), "r"(a2), "r"(a3), "r"(b0), "r"(b1));
}
__device__ __forceinline__ void split_pair(float a, float b, unsigned &hi, unsigned &lo) {
    __nv_bfloat16 ha = __float2bfloat16_rn(a), hb = __float2bfloat16_rn(b);
    float ra = a - __bfloat162float(ha), rb = b - __bfloat162float(hb);
    __nv_bfloat162 hv; hv.x = ha; hv.y = hb;
    __nv_bfloat162 lv; lv.x = __float2bfloat16_rn(ra); lv.y = __float2bfloat16_rn(rb);
    hi = *(unsigned*)&hv; lo = *(unsigned*)&lv;
}
__device__ __forceinline__ unsigned s2u(const void* p) {
    return (unsigned)__cvta_generic_to_shared(p);
}
__device__ __forceinline__ void cp16(unsigned dst, const void* src) {
    asm volatile("cp.async.cg.shared.global [%0], [%1], 16;" :: "r"(dst), "l"(src) : "memory");
}

// ---- x[b][c][n] -> packed split-bf16 + tf32, layout [b][n][c] ----
__global__ __launch_bounds__(256) void transpose_pack_k(const float* __restrict__ x,
                                                        unsigned* __restrict__ xts,
                                                        unsigned* __restrict__ xtt) {
    __shared__ float tl[32][33];
    const int b = blockIdx.z, c0 = blockIdx.y * 32, n0 = blockIdx.x * 32;
    const int tx = threadIdx.x & 31, ty = threadIdx.x >> 5;
    const float* xb = x + (size_t)b * CC * HWN;
#pragma unroll
    for (int i = 0; i < 4; ++i)
        tl[ty + 8 * i][tx] = xb[(size_t)(c0 + ty + 8 * i) * HWN + n0 + tx];
    __syncthreads();
    unsigned* xso = xts + (size_t)b * HWN * CC;
    unsigned* xto = xtt + (size_t)b * HWN * CC;
#pragma unroll
    for (int rep = 0; rep < 2; ++rep) {
        const int task = threadIdx.x + rep * 256;   // 512 tasks: 32 n x 16 c-pairs
        const int nl = task >> 4, p = task & 15;
        float f0 = tl[2 * p][nl], f1 = tl[2 * p + 1][nl];
        unsigned hi, lo;
        split_pair(f0, f1, hi, lo);
        const size_t base = (size_t)(n0 + nl) * CC + c0 + 2 * p;
        *(uint2*)&xso[base] = make_uint2(hi, lo);
        *(uint2*)&xto[base] = make_uint2(ftf(f0), ftf(f1));
    }
}

// ---- weight packers ----
__global__ __launch_bounds__(256) void pack_split_k(const float* __restrict__ src,
                                                    unsigned* __restrict__ dst, int npairs) {
    const int id = blockIdx.x * 256 + threadIdx.x;
    if (id >= npairs) return;
    float2 v = *(const float2*)&src[2 * id];
    unsigned hi, lo;
    split_pair(v.x, v.y, hi, lo);
    *(uint2*)&dst[2 * id] = make_uint2(hi, lo);
}
__global__ __launch_bounds__(256) void pack_tf32_k(const float* __restrict__ src,
                                                   unsigned* __restrict__ dst, int nquads) {
    const int id = blockIdx.x * 256 + threadIdx.x;
    if (id >= nquads) return;
    float4 v = *(const float4*)&src[4 * id];
    *(uint4*)&dst[4 * id] = make_uint4(ftf(v.x), ftf(v.y), ftf(v.z), ftf(v.w));
}

// ---- conv GEMM, pre-packed operands, cp.async double-buffered ----
// C[row][col] = A[row][:K].B[col][:K] + bias[col]; tile 128x128, 8 warps.
template<int K, bool PRECISE>
__global__ __launch_bounds__(256) void gemm2_k(const unsigned* __restrict__ A, long aStride,
                                               const unsigned* __restrict__ B,
                                               const float* __restrict__ bias,
                                               float* __restrict__ C, int ldc, long cStride) {
    extern __shared__ unsigned smu[];
    unsigned* Abuf = smu;               // 2 x 128 x 36
    unsigned* Bbuf = smu + 2 * 4608;    // 2 x 128 x 36
    const int b = blockIdx.z;
    const int row0 = blockIdx.x * 128, col0 = blockIdx.y * 128;
    const int tid = threadIdx.x, lane = tid & 31, wid = tid >> 5;
    const int g = lane >> 2, t = lane & 3;
    const int wm = (wid & 3) * 32, wn = (wid >> 2) * 64;
    const unsigned* Ag = A + (size_t)b * aStride + (size_t)row0 * K;
    const unsigned* Bg = B + (size_t)col0 * K;
    float* Cb = C + (size_t)b * cStride;

    const unsigned aBase = s2u(Abuf), bBase = s2u(Bbuf);
    auto stage = [&](int c) {
        const unsigned ab = aBase + (unsigned)((c & 1) * 4608 * 4);
        const unsigned bb = bBase + (unsigned)((c & 1) * 4608 * 4);
        const unsigned* Ac = Ag + c * 32;
        const unsigned* Bc = Bg + c * 32;
#pragma unroll
        for (int i = 0; i < 4; ++i) {
            const int id = tid + i * 256;
            const int row = id >> 3, q = id & 7;
            cp16(ab + (unsigned)((row * 36 + q * 4) * 4), Ac + (size_t)row * K + q * 4);
            cp16(bb + (unsigned)((row * 36 + q * 4) * 4), Bc + (size_t)row * K + q * 4);
        }
        asm volatile("cp.async.commit_group;" ::: "memory");
    };

    float acc[2][8][4];
#pragma unroll
    for (int mt = 0; mt < 2; ++mt)
#pragma unroll
        for (int j = 0; j < 8; ++j)
#pragma unroll
            for (int q = 0; q < 4; ++q) acc[mt][j][q] = 0.f;

    const int NC = K / 32;
    stage(0);
    for (int c = 0; c < NC; ++c) {
        if (c + 1 < NC) {
            stage(c + 1);
            asm volatile("cp.async.wait_group 1;" ::: "memory");
        } else {
            asm volatile("cp.async.wait_group 0;" ::: "memory");
        }
        __syncthreads();
        const unsigned* Asu = Abuf + (c & 1) * 4608;
        const unsigned* Bsu = Bbuf + (c & 1) * 4608;
        if (PRECISE) {
#pragma unroll
            for (int kk = 0; kk < 2; ++kk) {
                unsigned ah[2][4], al[2][4];
#pragma unroll
                for (int mt = 0; mt < 2; ++mt) {
                    const int rb = (wm + mt * 16 + g) * 36 + kk * 16 + 2 * t;
                    uint2 p0 = *(uint2*)&Asu[rb];
                    uint2 p1 = *(uint2*)&Asu[rb + 8 * 36];
                    uint2 p2 = *(uint2*)&Asu[rb + 8];
                    uint2 p3 = *(uint2*)&Asu[rb + 8 * 36 + 8];
                    ah[mt][0] = p0.x; al[mt][0] = p0.y;
                    ah[mt][1] = p1.x; al[mt][1] = p1.y;
                    ah[mt][2] = p2.x; al[mt][2] = p2.y;
                    ah[mt][3] = p3.x; al[mt][3] = p3.y;
                }
#pragma unroll
                for (int j = 0; j < 8; ++j) {
                    const int nb = (wn + 8 * j + g) * 36 + kk * 16 + 2 * t;
                    uint2 q0 = *(uint2*)&Bsu[nb];
                    uint2 q1 = *(uint2*)&Bsu[nb + 8];
#pragma unroll
                    for (int mt = 0; mt < 2; ++mt) {
                        mma16(acc[mt][j], ah[mt][0], ah[mt][1], ah[mt][2], ah[mt][3], q0.x, q1.x);
                        mma16(acc[mt][j], ah[mt][0], ah[mt][1], ah[mt][2], ah[mt][3], q0.y, q1.y);
                        mma16(acc[mt][j], al[mt][0], al[mt][1], al[mt][2], al[mt][3], q0.x, q1.x);
                    }
                }
            }
        } else {
#pragma unroll
            for (int kk = 0; kk < 4; ++kk) {
                unsigned a[2][4];
#pragma unroll
                for (int mt = 0; mt < 2; ++mt) {
                    const int rb = (wm + mt * 16 + g) * 36 + kk * 8 + t;
                    a[mt][0] = Asu[rb];
                    a[mt][1] = Asu[rb + 8 * 36];
                    a[mt][2] = Asu[rb + 4];
                    a[mt][3] = Asu[rb + 8 * 36 + 4];
                }
#pragma unroll
                for (int j = 0; j < 8; ++j) {
                    const int nb = (wn + 8 * j + g) * 36 + kk * 8 + t;
                    unsigned b0 = Bsu[nb], b1 = Bsu[nb + 4];
#pragma unroll
                    for (int mt = 0; mt < 2; ++mt)
                        mma8(acc[mt][j], a[mt][0], a[mt][1], a[mt][2], a[mt][3], b0, b1);
                }
            }
        }
        __syncthreads();
    }
#pragma unroll
    for (int mt = 0; mt < 2; ++mt)
#pragma unroll
        for (int j = 0; j < 8; ++j) {
            const int col = col0 + wn + 8 * j + 2 * t;
            float2 bv = *(const float2*)&bias[col];
            const int r = row0 + wm + mt * 16 + g;
            *(float2*)&Cb[(size_t)r * ldc + col] =
                make_float2(acc[mt][j][0] + bv.x, acc[mt][j][1] + bv.y);
            *(float2*)&Cb[(size_t)(r + 8) * ldc + col] =
                make_float2(acc[mt][j][2] + bv.x, acc[mt][j][3] + bv.y);
        }
}

// ---- pool + convert K (phi): split-bf16 packed ----
__global__ __launch_bounds__(256) void pool_splitk(const float* __restrict__ in,
                                                   unsigned* __restrict__ out) {
    const int gi = blockIdx.x * 256 + threadIdx.x;
    const int b = gi / (NP * 32);
    const int rem = gi - b * (NP * 32);
    const int m = rem >> 5, kq = rem & 31;
    const int ph = m >> 5, pw = m & 31;
    const int n00 = ph * 128 + pw * 2;
    const float* ib = in + (size_t)b * HWN * CI + (size_t)n00 * CI + kq * 4;
    float4 v0 = *(const float4*)ib;
    float4 v1 = *(const float4*)(ib + CI);
    float4 v2 = *(const float4*)(ib + 64 * CI);
    float4 v3 = *(const float4*)(ib + 65 * CI);
    float4 r;
    r.x = fmaxf(fmaxf(v0.x, v1.x), fmaxf(v2.x, v3.x));
    r.y = fmaxf(fmaxf(v0.y, v1.y), fmaxf(v2.y, v3.y));
    r.z = fmaxf(fmaxf(v0.z, v1.z), fmaxf(v2.z, v3.z));
    r.w = fmaxf(fmaxf(v0.w, v1.w), fmaxf(v2.w, v3.w));
    unsigned h0, l0, h1, l1;
    split_pair(r.x, r.y, h0, l0);
    split_pair(r.z, r.w, h1, l1);
    *(uint4*)&out[((size_t)b * NP + m) * 128 + kq * 4] = make_uint4(h0, l0, h1, l1);
}

// ---- pool + convert V (g): tf32 PV-interleaved ----
__global__ __launch_bounds__(256) void pool_vtf32(const float* __restrict__ in,
                                                  unsigned* __restrict__ out) {
    const int gi = blockIdx.x * 256 + threadIdx.x;
    const int b = gi / (NP * 32);
    const int rem = gi - b * (NP * 32);
    const int m = rem >> 5, kq = rem & 31;
    const int ph = m >> 5, pw = m & 31;
    const int n00 = ph * 128 + pw * 2;
    const float* ib = in + (size_t)b * HWN * CI + (size_t)n00 * CI + kq * 4;
    float4 v0 = *(const float4*)ib;
    float4 v1 = *(const float4*)(ib + CI);
    float4 v2 = *(const float4*)(ib + 64 * CI);
    float4 v3 = *(const float4*)(ib + 65 * CI);
    float4 r;
    r.x = fmaxf(fmaxf(v0.x, v1.x), fmaxf(v2.x, v3.x));
    r.y = fmaxf(fmaxf(v0.y, v1.y), fmaxf(v2.y, v3.y));
    r.z = fmaxf(fmaxf(v0.z, v1.z), fmaxf(v2.z, v3.z));
    r.w = fmaxf(fmaxf(v0.w, v1.w), fmaxf(v2.w, v3.w));
    const int ml = m & 63;
    unsigned* ob = out + (size_t)b * NP * 128 + (size_t)(m >> 6) * 8192;
    const int base = (ml >> 3) * 1024 + kq * 32 + (ml & 3) * 2 + ((ml >> 2) & 1);
    ob[base]      = ftf(r.x);
    ob[base + 8]  = ftf(r.y);
    ob[base + 16] = ftf(r.z);
    ob[base + 24] = ftf(r.w);
}

// ---- fused attention: Q frags in regs, cp.async double-buffered K/V ----
__global__ __launch_bounds__(256) void attn_k(const float* __restrict__ q,
                                              const unsigned* __restrict__ kpk,
                                              const unsigned* __restrict__ vpk,
                                              unsigned* __restrict__ y) {
    extern __shared__ float sm[];
    unsigned* ks  = (unsigned*)sm;       // 2 x 64 x 132
    unsigned* vs  = ks + 2 * 64 * 132;   // 2 x 8192
    unsigned* psu = vs + 2 * 8192;       // 128 x 68
    const int b = blockIdx.y, n0 = blockIdx.x * 128;
    const int tid = threadIdx.x, lane = tid & 31, wid = tid >> 5;
    const int g = lane >> 2, t = lane & 3;
    const int wrow = wid * 16;
    const float* qb = q + (size_t)b * HWN * CI;
    const unsigned* kg = kpk + (size_t)b * NP * 128;
    const unsigned* vg = vpk + (size_t)b * NP * 128;

    unsigned qh[8][4], ql[8][4];
    {
        const float* q0p = qb + (size_t)(n0 + wrow + g) * CI;
        const float* q1p = qb + (size_t)(n0 + wrow + g + 8) * CI;
#pragma unroll
        for (int kk = 0; kk < 8; ++kk) {
            float2 v0 = *(const float2*)&q0p[kk * 16 + 2 * t];
            float2 v1 = *(const float2*)&q1p[kk * 16 + 2 * t];
            float2 v2 = *(const float2*)&q0p[kk * 16 + 2 * t + 8];
            float2 v3 = *(const float2*)&q1p[kk * 16 + 2 * t + 8];
            split_pair(v0.x, v0.y, qh[kk][0], ql[kk][0]);
            split_pair(v1.x, v1.y, qh[kk][1], ql[kk][1]);
            split_pair(v2.x, v2.y, qh[kk][2], ql[kk][2]);
            split_pair(v3.x, v3.y, qh[kk][3], ql[kk][3]);
        }
    }

    const unsigned ksBase = s2u(ks), vsBase = s2u(vs);
    auto stage = [&](int it) {
        const unsigned kb = ksBase + (unsigned)((it & 1) * 64 * 132 * 4);
        const unsigned vb = vsBase + (unsigned)((it & 1) * 8192 * 4);
        const unsigned* kgt = kg + (size_t)it * 64 * 128;
        const unsigned* vgt = vg + (size_t)it * 8192;
#pragma unroll
        for (int i = 0; i < 8; ++i) {
            const int id = tid + i * 256;
            const int row = id >> 5, c = id & 31;
            cp16(kb + (unsigned)((row * 132 + c * 4) * 4), kgt + row * 128 + c * 4);
            cp16(vb + (unsigned)(id * 16), vgt + id * 4);
        }
        asm volatile("cp.async.commit_group;" ::: "memory");
    };

    stage(0);

    float o[16][4];
#pragma unroll
    for (int j = 0; j < 16; ++j)
#pragma unroll
        for (int qd = 0; qd < 4; ++qd) o[j][qd] = 0.f;
    float mr[2] = {-1e30f, -1e30f}, lr[2] = {0.f, 0.f};

    for (int iter = 0; iter < 16; ++iter) {
        if (iter < 15) {
            stage(iter + 1);
            asm volatile("cp.async.wait_group 1;" ::: "memory");
        } else {
            asm volatile("cp.async.wait_group 0;" ::: "memory");
        }
        __syncthreads();
        const unsigned* kbuf = ks + (iter & 1) * 64 * 132;
        const unsigned* vbuf = vs + (iter & 1) * 8192;

        float s[8][4];
#pragma unroll
        for (int j = 0; j < 8; ++j)
#pragma unroll
            for (int qd = 0; qd < 4; ++qd) s[j][qd] = 0.f;
#pragma unroll 4
        for (int kk = 0; kk < 8; ++kk) {
#pragma unroll
            for (int j = 0; j < 8; ++j) {
                const int kb2 = (8 * j + g) * 132 + kk * 16 + 2 * t;
                uint2 q0 = *(uint2*)&kbuf[kb2];
                uint2 q1 = *(uint2*)&kbuf[kb2 + 8];
                mma16(s[j], qh[kk][0], qh[kk][1], qh[kk][2], qh[kk][3], q0.x, q1.x);
                mma16(s[j], qh[kk][0], qh[kk][1], qh[kk][2], qh[kk][3], q0.y, q1.y);
                mma16(s[j], ql[kk][0], ql[kk][1], ql[kk][2], ql[kk][3], q0.x, q1.x);
            }
        }

#pragma unroll
        for (int r = 0; r < 2; ++r) {
            float tm = -1e30f;
#pragma unroll
            for (int j = 0; j < 8; ++j)
                tm = fmaxf(tm, fmaxf(s[j][2 * r], s[j][2 * r + 1]));
            tm = fmaxf(tm, __shfl_xor_sync(0xffffffffu, tm, 1));
            tm = fmaxf(tm, __shfl_xor_sync(0xffffffffu, tm, 2));
            const float mnew = fmaxf(mr[r], tm);
            const float scale = __expf(mr[r] - mnew);
            float sum = 0.f;
#pragma unroll
            for (int j = 0; j < 8; ++j) {
                float e0 = __expf(s[j][2 * r] - mnew);
                float e1 = __expf(s[j][2 * r + 1] - mnew);
                s[j][2 * r] = e0; s[j][2 * r + 1] = e1;
                sum += e0 + e1;
            }
            sum += __shfl_xor_sync(0xffffffffu, sum, 1);
            sum += __shfl_xor_sync(0xffffffffu, sum, 2);
            lr[r] = lr[r] * scale + sum;
            mr[r] = mnew;
#pragma unroll
            for (int jt = 0; jt < 16; ++jt) {
                o[jt][2 * r] *= scale; o[jt][2 * r + 1] *= scale;
            }
            const int prow = wrow + g + 8 * r;
#pragma unroll
            for (int j = 0; j < 8; ++j)
                *(uint2*)&psu[prow * 68 + 8 * j + 2 * t] =
                    make_uint2(ftf(s[j][2 * r]), ftf(s[j][2 * r + 1]));
        }
        __syncwarp();

#pragma unroll 2
        for (int kk = 0; kk < 8; ++kk) {
            const int pb = (wrow + g) * 68 + kk * 8 + t;
            unsigned a0 = psu[pb];
            unsigned a1 = psu[pb + 8 * 68];
            unsigned a2 = psu[pb + 4];
            unsigned a3 = psu[pb + 8 * 68 + 4];
#pragma unroll
            for (int j = 0; j < 16; ++j) {
                uint2 bp = *(uint2*)&vbuf[kk * 1024 + (8 * j + g) * 8 + t * 2];
                mma8(o[j], a0, a1, a2, a3, bp.x, bp.y);
            }
        }
        __syncthreads();
    }

    // epilogue: write y packed split-bf16 (W-conv A operand)
    const float inv0 = 1.f / lr[0], inv1 = 1.f / lr[1];
    unsigned* yb = y + (size_t)b * HWN * CI;
#pragma unroll
    for (int j = 0; j < 16; ++j) {
        const int col = 8 * j + 2 * t;
        unsigned hi, lo;
        split_pair(o[j][0] * inv0, o[j][1] * inv0, hi, lo);
        *(uint2*)&yb[(size_t)(n0 + wrow + g) * CI + col] = make_uint2(hi, lo);
        split_pair(o[j][2] * inv1, o[j][3] * inv1, hi, lo);
        *(uint2*)&yb[(size_t)(n0 + wrow + g + 8) * CI + col] = make_uint2(hi, lo);
    }
}

// ---- BN stats ----
__global__ __launch_bounds__(256) void bnpart_k(const float* __restrict__ wy) {
    const int p = blockIdx.x, t = threadIdx.x;
    const float* base = wy + (size_t)p * 256 * CC + t;
    float s = 0.f, s2 = 0.f;
#pragma unroll 4
    for (int r = 0; r < 256; ++r) {
        float v = base[(size_t)r * CC];
        s += v; s2 += v * v;
    }
    d_part[0][p][t] = s;
    d_part[1][p][t] = s2;
}

__global__ __launch_bounds__(256) void bnred_k(const float* __restrict__ inp0,
                                               float* __restrict__ out, int off) {
    const int t = threadIdx.x;
    double s = 0.0, s2 = 0.0;
    for (int p = 0; p < 256; ++p) {
        s += (double)d_part[0][p][t];
        s2 += (double)d_part[1][p][t];
    }
    const double cnt = (double)(BB * HWN);
    const double mean = s / cnt;
    const double var = s2 / cnt - mean * mean;
    d_mean[t] = (float)mean;
    d_rstd[t] = (float)rsqrt(var + 1e-5);
    if (t == 0 && off == 1) out[0] = inp0[0];
}

// ---- BN apply + residual + transpose back to [b][co][n] ----
__global__ __launch_bounds__(256) void finalT_k(const float* __restrict__ wy,
                                                const float* __restrict__ x,
                                                const float* __restrict__ gamma,
                                                const float* __restrict__ beta,
                                                float* __restrict__ out, int off) {
    __shared__ float tl[32][33];
    const int b = blockIdx.z, co0 = blockIdx.y * 32, n0 = blockIdx.x * 32;
    const int tx = threadIdx.x & 31, ty = threadIdx.x >> 5;
    const float* wb = wy + (size_t)b * HWN * CC;
#pragma unroll
    for (int i = 0; i < 4; ++i)
        tl[ty + 8 * i][tx] = wb[(size_t)(n0 + ty + 8 * i) * CC + co0 + tx];
    __syncthreads();
#pragma unroll
    for (int i = 0; i < 4; ++i) {
        const int co = co0 + ty + 8 * i;
        const float a = d_rstd[co] * gamma[co];
        const float bb2 = beta[co] - d_mean[co] * a;
        const size_t idx = (size_t)b * CC * HWN + (size_t)co * HWN + n0 + tx;
        out[off + idx] = tl[tx][ty + 8 * i] * a + bb2 + x[idx];
    }
}

extern "C" void kernel_launch(void* const* d_in, const int* in_sizes, int n_in,
                              void* d_out, int out_size) {
    const float* inp0 = (const float*)d_in[0];
    const float* x    = (const float*)d_in[1];
    const float* g_w  = (const float*)d_in[2];
    const float* g_b  = (const float*)d_in[3];
    const float* th_w = (const float*)d_in[4];
    const float* th_b = (const float*)d_in[5];
    const float* ph_w = (const float*)d_in[6];
    const float* ph_b = (const float*)d_in[7];
    const float* W_w  = (const float*)d_in[8];
    const float* W_b  = (const float*)d_in[9];
    const float* gam  = (const float*)d_in[10];
    const float* bet  = (const float*)d_in[11];
    float* out = (float*)d_out;

    float *p_theta, *p_gf, *p_pf, *p_wy;
    unsigned *p_xts, *p_xtt, *p_kp, *p_vp, *p_yp, *p_wth, *p_wph, *p_wg, *p_ww;
    cudaGetSymbolAddress((void**)&p_xts, d_xts);
    cudaGetSymbolAddress((void**)&p_xtt, d_xtt);
    cudaGetSymbolAddress((void**)&p_theta, d_theta);
    cudaGetSymbolAddress((void**)&p_gf, d_gf);
    cudaGetSymbolAddress((void**)&p_pf, d_pf);
    cudaGetSymbolAddress((void**)&p_kp, d_kpack);
    cudaGetSymbolAddress((void**)&p_vp, d_vpack);
    cudaGetSymbolAddress((void**)&p_yp, d_ypack);
    cudaGetSymbolAddress((void**)&p_wy, d_wy);
    cudaGetSymbolAddress((void**)&p_wth, d_wth);
    cudaGetSymbolAddress((void**)&p_wph, d_wph);
    cudaGetSymbolAddress((void**)&p_wg, d_wg);
    cudaGetSymbolAddress((void**)&p_ww, d_ww);

    const int GEMM2_SMEM = 4 * 4608 * 4;                             // 73728
    const int ATTN_SMEM = (2 * 64 * 132 + 2 * 8192 + 128 * 68) * 4;  // 167936
    cudaFuncSetAttribute(gemm2_k<256, true>,  cudaFuncAttributeMaxDynamicSharedMemorySize, GEMM2_SMEM);
    cudaFuncSetAttribute(gemm2_k<128, true>,  cudaFuncAttributeMaxDynamicSharedMemorySize, GEMM2_SMEM);
    cudaFuncSetAttribute(gemm2_k<256, false>, cudaFuncAttributeMaxDynamicSharedMemorySize, GEMM2_SMEM);
    cudaFuncSetAttribute(attn_k, cudaFuncAttributeMaxDynamicSharedMemorySize, ATTN_SMEM);

    transpose_pack_k<<<dim3(HWN / 32, CC / 32, BB), 256>>>(x, p_xts, p_xtt);
    pack_split_k<<<(CI * CC / 2 + 255) / 256, 256>>>(th_w, p_wth, CI * CC / 2);
    pack_split_k<<<(CI * CC / 2 + 255) / 256, 256>>>(ph_w, p_wph, CI * CC / 2);
    pack_tf32_k<<<(CI * CC / 4 + 255) / 256, 256>>>(g_w, p_wg, CI * CC / 4);
    pack_split_k<<<(CC * CI / 2 + 255) / 256, 256>>>(W_w, p_ww, CC * CI / 2);

    gemm2_k<256, true><<<dim3(32, 1, BB), 256, GEMM2_SMEM>>>(
        p_xts, (long)HWN * CC, p_wth, th_b, p_theta, CI, (long)HWN * CI);
    gemm2_k<256, true><<<dim3(32, 1, BB), 256, GEMM2_SMEM>>>(
        p_xts, (long)HWN * CC, p_wph, ph_b, p_pf, CI, (long)HWN * CI);
    gemm2_k<256, false><<<dim3(32, 1, BB), 256, GEMM2_SMEM>>>(
        p_xtt, (long)HWN * CC, p_wg, g_b, p_gf, CI, (long)HWN * CI);

    pool_splitk<<<(BB * NP * 32) / 256, 256>>>(p_pf, p_kp);
    pool_vtf32<<<(BB * NP * 32) / 256, 256>>>(p_gf, p_vp);

    attn_k<<<dim3(HWN / 128, BB), 256, ATTN_SMEM>>>(p_theta, p_kp, p_vp, p_yp);

    gemm2_k<128, true><<<dim3(32, 2, BB), 256, GEMM2_SMEM>>>(
        p_yp, (long)HWN * CI, p_ww, W_b, p_wy, CC, (long)HWN * CC);

    bnpart_k<<<256, 256>>>(p_wy);

    const int total = BB * CC * HWN;
    const int off = (out_size > total) ? (out_size - total) : 0;
    bnred_k<<<1, 256>>>(inp0, out, off);

    finalT_k<<<dim3(HWN / 32, CC / 32, BB), 256>>>(p_wy, x, gam, bet, out, off);
}

// round 9
// speedup vs baseline: 3.5096x; 1.0447x over previous
#include <cuda_runtime.h>
#include <cuda_bf16.h>
#include <math.h>

#define BB   16
#define CC   256
#define CI   128
#define HWN  4096
#define NP   1024

__device__ unsigned d_xts[BB * HWN * CC];    // x^T packed split-bf16
__device__ unsigned d_xtt[BB * HWN * CC];    // x^T tf32
__device__ unsigned d_qpack[BB * HWN * CI];  // theta out, split-bf16 packed (Q)
__device__ unsigned d_kpack[BB * NP * 128];  // phi pooled, split-bf16 packed
__device__ unsigned d_vpack[BB * NP * 128];  // g pooled, tf32 PV-interleaved
__device__ unsigned d_ypack[BB * HWN * CI];  // attn out, split-bf16 packed
__device__ float    d_wy[BB * HWN * CC];     // W conv out channel-last
__device__ unsigned d_wth[CI * CC];
__device__ unsigned d_wph[CI * CC];
__device__ unsigned d_wg[CI * CC];
__device__ unsigned d_ww[CC * CI];
__device__ float d_part[2][256][256];
__device__ float d_mean[CC];
__device__ float d_rstd[CC];

__device__ __forceinline__ unsigned ftf(float x) {
    unsigned u; asm("cvt.rna.tf32.f32 %0,%1;" : "=r"(u) : "f"(x)); return u;
}
// tf32 m16n8k8: a0=A[g][t] a1=A[g+8][t] a2=A[g][t+4] a3=A[g+8][t+4]; b0=B[n][t] b1=B[n][t+4]
__device__ __forceinline__ void mma8(float* c, unsigned a0, unsigned a1, unsigned a2, unsigned a3,
                                     unsigned b0, unsigned b1) {
    asm volatile("mma.sync.aligned.m16n8k8.row.col.f32.tf32.tf32.f32 "
                 "{%0,%1,%2,%3},{%4,%5,%6,%7},{%8,%9},{%0,%1,%2,%3};"
                 : "+f"(c[0]), "+f"(c[1]), "+f"(c[2]), "+f"(c[3])
                 : "r"(a0), "r"(a1), "r"(a2), "r"(a3), "r"(b0), "r"(b1));
}
// bf16 m16n8k16: a0=A[g][2t,2t+1] a1=A[g+8][..] a2=A[g][2t+8,..] a3=A[g+8][2t+8,..]
__device__ __forceinline__ void mma16(float* c, unsigned a0, unsigned a1, unsigned a2, unsigned a3,
                                      unsigned b0, unsigned b1) {
    asm volatile("mma.sync.aligned.m16n8k16.row.col.f32.bf16.bf16.f32 "
                 "{%0,%1,%2,%3},{%4,%5,%6,%7},{%8,%9},{%0,%1,%2,%3};"
                 : "+f"(c[0]), "+f"(c[1]), "+f"(c[2]), "+f"(c[3])
                 : "r"(a0), "r"(a1), "r"(a2), "r"(a3), "r"(b0), "r"(b1));
}
__device__ __forceinline__ void split_pair(float a, float b, unsigned &hi, unsigned &lo) {
    __nv_bfloat16 ha = __float2bfloat16_rn(a), hb = __float2bfloat16_rn(b);
    float ra = a - __bfloat162float(ha), rb = b - __bfloat162float(hb);
    __nv_bfloat162 hv; hv.x = ha; hv.y = hb;
    __nv_bfloat162 lv; lv.x = __float2bfloat16_rn(ra); lv.y = __float2bfloat16_rn(rb);
    hi = *(unsigned*)&hv; lo = *(unsigned*)&lv;
}
__device__ __forceinline__ unsigned s2u(const void* p) {
    return (unsigned)__cvta_generic_to_shared(p);
}
__device__ __forceinline__ void cp16(unsigned dst, const void* src) {
    asm volatile("cp.async.cg.shared.global [%0], [%1], 16;" :: "r"(dst), "l"(src) : "memory");
}

// ---- x[b][c][n] -> packed split-bf16 + tf32, layout [b][n][c] ----
__global__ __launch_bounds__(256) void transpose_pack_k(const float* __restrict__ x,
                                                        unsigned* __restrict__ xts,
                                                        unsigned* __restrict__ xtt) {
    __shared__ float tl[32][33];
    const int b = blockIdx.z, c0 = blockIdx.y * 32, n0 = blockIdx.x * 32;
    const int tx = threadIdx.x & 31, ty = threadIdx.x >> 5;
    const float* xb = x + (size_t)b * CC * HWN;
#pragma unroll
    for (int i = 0; i < 4; ++i)
        tl[ty + 8 * i][tx] = xb[(size_t)(c0 + ty + 8 * i) * HWN + n0 + tx];
    __syncthreads();
    unsigned* xso = xts + (size_t)b * HWN * CC;
    unsigned* xto = xtt + (size_t)b * HWN * CC;
#pragma unroll
    for (int rep = 0; rep < 2; ++rep) {
        const int task = threadIdx.x + rep * 256;
        const int nl = task >> 4, p = task & 15;
        float f0 = tl[2 * p][nl], f1 = tl[2 * p + 1][nl];
        unsigned hi, lo;
        split_pair(f0, f1, hi, lo);
        const size_t base = (size_t)(n0 + nl) * CC + c0 + 2 * p;
        *(uint2*)&xso[base] = make_uint2(hi, lo);
        *(uint2*)&xto[base] = make_uint2(ftf(f0), ftf(f1));
    }
}

// ---- weight packers ----
__global__ __launch_bounds__(256) void pack_split_k(const float* __restrict__ src,
                                                    unsigned* __restrict__ dst, int npairs) {
    const int id = blockIdx.x * 256 + threadIdx.x;
    if (id >= npairs) return;
    float2 v = *(const float2*)&src[2 * id];
    unsigned hi, lo;
    split_pair(v.x, v.y, hi, lo);
    *(uint2*)&dst[2 * id] = make_uint2(hi, lo);
}
__global__ __launch_bounds__(256) void pack_tf32_k(const float* __restrict__ src,
                                                   unsigned* __restrict__ dst, int nquads) {
    const int id = blockIdx.x * 256 + threadIdx.x;
    if (id >= nquads) return;
    float4 v = *(const float4*)&src[4 * id];
    *(uint4*)&dst[4 * id] = make_uint4(ftf(v.x), ftf(v.y), ftf(v.z), ftf(v.w));
}

// ---- conv GEMM, pre-packed operands, cp.async double-buffered ----
// OUTMODE: 0 = fp32 C; 1 = packed split-bf16 C; 2 = 2x2-pool + split-bf16 (kpack);
//          3 = 2x2-pool + tf32 PV-interleaved (vpack). Modes 2/3 require grid.y==1.
template<int K, bool PRECISE, int OUTMODE>
__global__ __launch_bounds__(256) void gemm2_k(const unsigned* __restrict__ A, long aStride,
                                               const unsigned* __restrict__ B,
                                               const float* __restrict__ bias,
                                               float* __restrict__ C, int ldc, long cStride) {
    extern __shared__ unsigned smu[];
    unsigned* Abuf = smu;               // 2 x 128 x 36
    unsigned* Bbuf = smu + 2 * 4608;    // 2 x 128 x 36
    const int b = blockIdx.z;
    const int row0 = blockIdx.x * 128, col0 = blockIdx.y * 128;
    const int tid = threadIdx.x, lane = tid & 31, wid = tid >> 5;
    const int g = lane >> 2, t = lane & 3;
    const int wm = (wid & 3) * 32, wn = (wid >> 2) * 64;
    const unsigned* Ag = A + (size_t)b * aStride + (size_t)row0 * K;
    const unsigned* Bg = B + (size_t)col0 * K;

    const unsigned aBase = s2u(Abuf), bBase = s2u(Bbuf);
    auto stage = [&](int c) {
        const unsigned ab = aBase + (unsigned)((c & 1) * 4608 * 4);
        const unsigned bb = bBase + (unsigned)((c & 1) * 4608 * 4);
        const unsigned* Ac = Ag + c * 32;
        const unsigned* Bc = Bg + c * 32;
#pragma unroll
        for (int i = 0; i < 4; ++i) {
            const int id = tid + i * 256;
            const int row = id >> 3, q = id & 7;
            cp16(ab + (unsigned)((row * 36 + q * 4) * 4), Ac + (size_t)row * K + q * 4);
            cp16(bb + (unsigned)((row * 36 + q * 4) * 4), Bc + (size_t)row * K + q * 4);
        }
        asm volatile("cp.async.commit_group;" ::: "memory");
    };

    float acc[2][8][4];
#pragma unroll
    for (int mt = 0; mt < 2; ++mt)
#pragma unroll
        for (int j = 0; j < 8; ++j)
#pragma unroll
            for (int q = 0; q < 4; ++q) acc[mt][j][q] = 0.f;

    const int NC = K / 32;
    stage(0);
    for (int c = 0; c < NC; ++c) {
        if (c + 1 < NC) {
            stage(c + 1);
            asm volatile("cp.async.wait_group 1;" ::: "memory");
        } else {
            asm volatile("cp.async.wait_group 0;" ::: "memory");
        }
        __syncthreads();
        const unsigned* Asu = Abuf + (c & 1) * 4608;
        const unsigned* Bsu = Bbuf + (c & 1) * 4608;
        if (PRECISE) {
#pragma unroll
            for (int kk = 0; kk < 2; ++kk) {
                unsigned ah[2][4], al[2][4];
#pragma unroll
                for (int mt = 0; mt < 2; ++mt) {
                    const int rb = (wm + mt * 16 + g) * 36 + kk * 16 + 2 * t;
                    uint2 p0 = *(uint2*)&Asu[rb];
                    uint2 p1 = *(uint2*)&Asu[rb + 8 * 36];
                    uint2 p2 = *(uint2*)&Asu[rb + 8];
                    uint2 p3 = *(uint2*)&Asu[rb + 8 * 36 + 8];
                    ah[mt][0] = p0.x; al[mt][0] = p0.y;
                    ah[mt][1] = p1.x; al[mt][1] = p1.y;
                    ah[mt][2] = p2.x; al[mt][2] = p2.y;
                    ah[mt][3] = p3.x; al[mt][3] = p3.y;
                }
#pragma unroll
                for (int j = 0; j < 8; ++j) {
                    const int nb = (wn + 8 * j + g) * 36 + kk * 16 + 2 * t;
                    uint2 q0 = *(uint2*)&Bsu[nb];
                    uint2 q1 = *(uint2*)&Bsu[nb + 8];
#pragma unroll
                    for (int mt = 0; mt < 2; ++mt) {
                        mma16(acc[mt][j], ah[mt][0], ah[mt][1], ah[mt][2], ah[mt][3], q0.x, q1.x);
                        mma16(acc[mt][j], ah[mt][0], ah[mt][1], ah[mt][2], ah[mt][3], q0.y, q1.y);
                        mma16(acc[mt][j], al[mt][0], al[mt][1], al[mt][2], al[mt][3], q0.x, q1.x);
                    }
                }
            }
        } else {
#pragma unroll
            for (int kk = 0; kk < 4; ++kk) {
                unsigned a[2][4];
#pragma unroll
                for (int mt = 0; mt < 2; ++mt) {
                    const int rb = (wm + mt * 16 + g) * 36 + kk * 8 + t;
                    a[mt][0] = Asu[rb];
                    a[mt][1] = Asu[rb + 8 * 36];
                    a[mt][2] = Asu[rb + 4];
                    a[mt][3] = Asu[rb + 8 * 36 + 4];
                }
#pragma unroll
                for (int j = 0; j < 8; ++j) {
                    const int nb = (wn + 8 * j + g) * 36 + kk * 8 + t;
                    unsigned b0 = Bsu[nb], b1 = Bsu[nb + 4];
#pragma unroll
                    for (int mt = 0; mt < 2; ++mt)
                        mma8(acc[mt][j], a[mt][0], a[mt][1], a[mt][2], a[mt][3], b0, b1);
                }
            }
        }
        __syncthreads();
    }

    if (OUTMODE == 0) {
        float* Cb = C + (size_t)b * cStride;
#pragma unroll
        for (int mt = 0; mt < 2; ++mt)
#pragma unroll
            for (int j = 0; j < 8; ++j) {
                const int col = col0 + wn + 8 * j + 2 * t;
                float2 bv = *(const float2*)&bias[col];
                const int r = row0 + wm + mt * 16 + g;
                *(float2*)&Cb[(size_t)r * ldc + col] =
                    make_float2(acc[mt][j][0] + bv.x, acc[mt][j][1] + bv.y);
                *(float2*)&Cb[(size_t)(r + 8) * ldc + col] =
                    make_float2(acc[mt][j][2] + bv.x, acc[mt][j][3] + bv.y);
            }
    } else if (OUTMODE == 1) {
        unsigned* Cp = (unsigned*)C + (size_t)b * cStride;
#pragma unroll
        for (int mt = 0; mt < 2; ++mt)
#pragma unroll
            for (int j = 0; j < 8; ++j) {
                const int col = col0 + wn + 8 * j + 2 * t;
                float2 bv = *(const float2*)&bias[col];
                const int r = row0 + wm + mt * 16 + g;
                unsigned hi, lo;
                split_pair(acc[mt][j][0] + bv.x, acc[mt][j][1] + bv.y, hi, lo);
                *(uint2*)&Cp[(size_t)r * ldc + col] = make_uint2(hi, lo);
                split_pair(acc[mt][j][2] + bv.x, acc[mt][j][3] + bv.y, hi, lo);
                *(uint2*)&Cp[(size_t)(r + 8) * ldc + col] = make_uint2(hi, lo);
            }
    } else {
        // pool modes: dump tile to SMEM (128x132 fp32), 2x2 maxpool, pack.
        float* ts = (float*)smu;
#pragma unroll
        for (int mt = 0; mt < 2; ++mt)
#pragma unroll
            for (int j = 0; j < 8; ++j) {
                const int cl = wn + 8 * j + 2 * t;
                float2 bv = *(const float2*)&bias[col0 + cl];
                float* r0p = &ts[(wm + mt * 16 + g) * 132 + cl];
                r0p[0] = acc[mt][j][0] + bv.x;  r0p[1] = acc[mt][j][1] + bv.y;
                float* r1p = r0p + 8 * 132;
                r1p[0] = acc[mt][j][2] + bv.x;  r1p[1] = acc[mt][j][3] + bv.y;
            }
        __syncthreads();
        const int ph = blockIdx.x;
        unsigned* Op = (unsigned*)C;
#pragma unroll
        for (int rep = 0; rep < 4; ++rep) {
            const int task = tid + rep * 256;       // 1024 tasks: 32 m x 32 kq
            const int mloc = task >> 5, kq = task & 31;
            const float* t0 = &ts[(2 * mloc) * 132 + kq * 4];
            float4 v0 = *(const float4*)t0;
            float4 v1 = *(const float4*)(t0 + 132);
            float4 v2 = *(const float4*)(t0 + 64 * 132);
            float4 v3 = *(const float4*)(t0 + 65 * 132);
            float4 rr;
            rr.x = fmaxf(fmaxf(v0.x, v1.x), fmaxf(v2.x, v3.x));
            rr.y = fmaxf(fmaxf(v0.y, v1.y), fmaxf(v2.y, v3.y));
            rr.z = fmaxf(fmaxf(v0.z, v1.z), fmaxf(v2.z, v3.z));
            rr.w = fmaxf(fmaxf(v0.w, v1.w), fmaxf(v2.w, v3.w));
            const int m = ph * 32 + mloc;
            if (OUTMODE == 2) {
                unsigned h0, l0, h1, l1;
                split_pair(rr.x, rr.y, h0, l0);
                split_pair(rr.z, rr.w, h1, l1);
                *(uint4*)&Op[((size_t)b * NP + m) * 128 + kq * 4] = make_uint4(h0, l0, h1, l1);
            } else {
                const int ml = m & 63;
                unsigned* ob = Op + (size_t)b * NP * 128 + (size_t)(m >> 6) * 8192;
                const int base = (ml >> 3) * 1024 + kq * 32 + (ml & 3) * 2 + ((ml >> 2) & 1);
                ob[base]      = ftf(rr.x);
                ob[base + 8]  = ftf(rr.y);
                ob[base + 16] = ftf(rr.z);
                ob[base + 24] = ftf(rr.w);
            }
        }
    }
}

// ---- fused attention: packed Q frags in regs, cp.async K/V, 1 barrier/tile ----
__global__ __launch_bounds__(256) void attn_k(const unsigned* __restrict__ qpk,
                                              const unsigned* __restrict__ kpk,
                                              const unsigned* __restrict__ vpk,
                                              unsigned* __restrict__ y) {
    extern __shared__ float sm[];
    unsigned* ks  = (unsigned*)sm;       // 2 x 64 x 132
    unsigned* vs  = ks + 2 * 64 * 132;   // 2 x 8192
    unsigned* psu = vs + 2 * 8192;       // 128 x 68
    const int b = blockIdx.y, n0 = blockIdx.x * 128;
    const int tid = threadIdx.x, lane = tid & 31, wid = tid >> 5;
    const int g = lane >> 2, t = lane & 3;
    const int wrow = wid * 16;
    const unsigned* kg = kpk + (size_t)b * NP * 128;
    const unsigned* vg = vpk + (size_t)b * NP * 128;

    // Q fragments straight from packed words: pair p -> words 2p (hi), 2p+1 (lo)
    unsigned qh[8][4], ql[8][4];
    {
        const unsigned* q0p = qpk + (size_t)b * HWN * CI + (size_t)(n0 + wrow + g) * CI;
        const unsigned* q1p = q0p + 8 * CI;
#pragma unroll
        for (int kk = 0; kk < 8; ++kk) {
            uint2 u0 = *(const uint2*)&q0p[kk * 16 + 2 * t];
            uint2 u1 = *(const uint2*)&q1p[kk * 16 + 2 * t];
            uint2 u2 = *(const uint2*)&q0p[kk * 16 + 2 * t + 8];
            uint2 u3 = *(const uint2*)&q1p[kk * 16 + 2 * t + 8];
            qh[kk][0] = u0.x; ql[kk][0] = u0.y;
            qh[kk][1] = u1.x; ql[kk][1] = u1.y;
            qh[kk][2] = u2.x; ql[kk][2] = u2.y;
            qh[kk][3] = u3.x; ql[kk][3] = u3.y;
        }
    }

    const unsigned ksBase = s2u(ks), vsBase = s2u(vs);
    auto stage = [&](int it) {
        const unsigned kb = ksBase + (unsigned)((it & 1) * 64 * 132 * 4);
        const unsigned vb = vsBase + (unsigned)((it & 1) * 8192 * 4);
        const unsigned* kgt = kg + (size_t)it * 64 * 128;
        const unsigned* vgt = vg + (size_t)it * 8192;
#pragma unroll
        for (int i = 0; i < 8; ++i) {
            const int id = tid + i * 256;
            const int row = id >> 5, c = id & 31;
            cp16(kb + (unsigned)((row * 132 + c * 4) * 4), kgt + row * 128 + c * 4);
            cp16(vb + (unsigned)(id * 16), vgt + id * 4);
        }
        asm volatile("cp.async.commit_group;" ::: "memory");
    };

    stage(0);

    float o[16][4];
#pragma unroll
    for (int j = 0; j < 16; ++j)
#pragma unroll
        for (int qd = 0; qd < 4; ++qd) o[j][qd] = 0.f;
    float mr[2] = {-1e30f, -1e30f}, lr[2] = {0.f, 0.f};

    for (int iter = 0; iter < 16; ++iter) {
        asm volatile("cp.async.wait_group 0;" ::: "memory");
        __syncthreads();   // staged data visible; also orders prev PV before next stage
        const unsigned* kbuf = ks + (iter & 1) * 64 * 132;
        const unsigned* vbuf = vs + (iter & 1) * 8192;

        // S = Q K^T (3-term split-bf16)
        float s[8][4];
#pragma unroll
        for (int j = 0; j < 8; ++j)
#pragma unroll
            for (int qd = 0; qd < 4; ++qd) s[j][qd] = 0.f;
#pragma unroll 4
        for (int kk = 0; kk < 8; ++kk) {
#pragma unroll
            for (int j = 0; j < 8; ++j) {
                const int kb2 = (8 * j + g) * 132 + kk * 16 + 2 * t;
                uint2 q0 = *(uint2*)&kbuf[kb2];
                uint2 q1 = *(uint2*)&kbuf[kb2 + 8];
                mma16(s[j], qh[kk][0], qh[kk][1], qh[kk][2], qh[kk][3], q0.x, q1.x);
                mma16(s[j], qh[kk][0], qh[kk][1], qh[kk][2], qh[kk][3], q0.y, q1.y);
                mma16(s[j], ql[kk][0], ql[kk][1], ql[kk][2], ql[kk][3], q0.x, q1.x);
            }
        }

        // online softmax, lazy O-rescale
#pragma unroll
        for (int r = 0; r < 2; ++r) {
            float tm = -1e30f;
#pragma unroll
            for (int j = 0; j < 8; ++j)
                tm = fmaxf(tm, fmaxf(s[j][2 * r], s[j][2 * r + 1]));
            tm = fmaxf(tm, __shfl_xor_sync(0xffffffffu, tm, 1));
            tm = fmaxf(tm, __shfl_xor_sync(0xffffffffu, tm, 2));
            const float mnew = fmaxf(mr[r], tm);
            const float scale = __expf(mr[r] - mnew);
            float sum = 0.f;
#pragma unroll
            for (int j = 0; j < 8; ++j) {
                float e0 = __expf(s[j][2 * r] - mnew);
                float e1 = __expf(s[j][2 * r + 1] - mnew);
                s[j][2 * r] = e0; s[j][2 * r + 1] = e1;
                sum += e0 + e1;
            }
            sum += __shfl_xor_sync(0xffffffffu, sum, 1);
            sum += __shfl_xor_sync(0xffffffffu, sum, 2);
            lr[r] = lr[r] * scale + sum;
            const bool rescale = !__all_sync(0xffffffffu, mnew == mr[r]);
            mr[r] = mnew;
            if (rescale) {
#pragma unroll
                for (int jt = 0; jt < 16; ++jt) {
                    o[jt][2 * r] *= scale; o[jt][2 * r + 1] *= scale;
                }
            }
            const int prow = wrow + g + 8 * r;
#pragma unroll
            for (int j = 0; j < 8; ++j)
                *(uint2*)&psu[prow * 68 + 8 * j + 2 * t] =
                    make_uint2(ftf(s[j][2 * r]), ftf(s[j][2 * r + 1]));
        }
        __syncwarp();

        // prefetch next tile into the other buffer (overlaps with PV below)
        if (iter < 15) stage(iter + 1);

        // O += P V (plain tf32)
#pragma unroll 2
        for (int kk = 0; kk < 8; ++kk) {
            const int pb = (wrow + g) * 68 + kk * 8 + t;
            unsigned a0 = psu[pb];
            unsigned a1 = psu[pb + 8 * 68];
            unsigned a2 = psu[pb + 4];
            unsigned a3 = psu[pb + 8 * 68 + 4];
#pragma unroll
            for (int j = 0; j < 16; ++j) {
                uint2 bp = *(uint2*)&vbuf[kk * 1024 + (8 * j + g) * 8 + t * 2];
                mma8(o[j], a0, a1, a2, a3, bp.x, bp.y);
            }
        }
    }

    // epilogue: write y packed split-bf16
    const float inv0 = 1.f / lr[0], inv1 = 1.f / lr[1];
    unsigned* yb = y + (size_t)b * HWN * CI;
#pragma unroll
    for (int j = 0; j < 16; ++j) {
        const int col = 8 * j + 2 * t;
        unsigned hi, lo;
        split_pair(o[j][0] * inv0, o[j][1] * inv0, hi, lo);
        *(uint2*)&yb[(size_t)(n0 + wrow + g) * CI + col] = make_uint2(hi, lo);
        split_pair(o[j][2] * inv1, o[j][3] * inv1, hi, lo);
        *(uint2*)&yb[(size_t)(n0 + wrow + g + 8) * CI + col] = make_uint2(hi, lo);
    }
}

// ---- BN stats ----
__global__ __launch_bounds__(256) void bnpart_k(const float* __restrict__ wy) {
    const int p = blockIdx.x, t = threadIdx.x;
    const float* base = wy + (size_t)p * 256 * CC + t;
    float s = 0.f, s2 = 0.f;
#pragma unroll 4
    for (int r = 0; r < 256; ++r) {
        float v = base[(size_t)r * CC];
        s += v; s2 += v * v;
    }
    d_part[0][p][t] = s;
    d_part[1][p][t] = s2;
}

__global__ __launch_bounds__(256) void bnred_k(const float* __restrict__ inp0,
                                               float* __restrict__ out, int off) {
    const int t = threadIdx.x;
    double s = 0.0, s2 = 0.0;
    for (int p = 0; p < 256; ++p) {
        s += (double)d_part[0][p][t];
        s2 += (double)d_part[1][p][t];
    }
    const double cnt = (double)(BB * HWN);
    const double mean = s / cnt;
    const double var = s2 / cnt - mean * mean;
    d_mean[t] = (float)mean;
    d_rstd[t] = (float)rsqrt(var + 1e-5);
    if (t == 0 && off == 1) out[0] = inp0[0];
}

// ---- BN apply + residual + transpose back to [b][co][n] ----
__global__ __launch_bounds__(256) void finalT_k(const float* __restrict__ wy,
                                                const float* __restrict__ x,
                                                const float* __restrict__ gamma,
                                                const float* __restrict__ beta,
                                                float* __restrict__ out, int off) {
    __shared__ float tl[32][33];
    const int b = blockIdx.z, co0 = blockIdx.y * 32, n0 = blockIdx.x * 32;
    const int tx = threadIdx.x & 31, ty = threadIdx.x >> 5;
    const float* wb = wy + (size_t)b * HWN * CC;
#pragma unroll
    for (int i = 0; i < 4; ++i)
        tl[ty + 8 * i][tx] = wb[(size_t)(n0 + ty + 8 * i) * CC + co0 + tx];
    __syncthreads();
#pragma unroll
    for (int i = 0; i < 4; ++i) {
        const int co = co0 + ty + 8 * i;
        const float a = d_rstd[co] * gamma[co];
        const float bb2 = beta[co] - d_mean[co] * a;
        const size_t idx = (size_t)b * CC * HWN + (size_t)co * HWN + n0 + tx;
        out[off + idx] = tl[tx][ty + 8 * i] * a + bb2 + x[idx];
    }
}

extern "C" void kernel_launch(void* const* d_in, const int* in_sizes, int n_in,
                              void* d_out, int out_size) {
    const float* inp0 = (const float*)d_in[0];
    const float* x    = (const float*)d_in[1];
    const float* g_w  = (const float*)d_in[2];
    const float* g_b  = (const float*)d_in[3];
    const float* th_w = (const float*)d_in[4];
    const float* th_b = (const float*)d_in[5];
    const float* ph_w = (const float*)d_in[6];
    const float* ph_b = (const float*)d_in[7];
    const float* W_w  = (const float*)d_in[8];
    const float* W_b  = (const float*)d_in[9];
    const float* gam  = (const float*)d_in[10];
    const float* bet  = (const float*)d_in[11];
    float* out = (float*)d_out;

    float* p_wy;
    unsigned *p_xts, *p_xtt, *p_qp, *p_kp, *p_vp, *p_yp, *p_wth, *p_wph, *p_wg, *p_ww;
    cudaGetSymbolAddress((void**)&p_xts, d_xts);
    cudaGetSymbolAddress((void**)&p_xtt, d_xtt);
    cudaGetSymbolAddress((void**)&p_qp, d_qpack);
    cudaGetSymbolAddress((void**)&p_kp, d_kpack);
    cudaGetSymbolAddress((void**)&p_vp, d_vpack);
    cudaGetSymbolAddress((void**)&p_yp, d_ypack);
    cudaGetSymbolAddress((void**)&p_wy, d_wy);
    cudaGetSymbolAddress((void**)&p_wth, d_wth);
    cudaGetSymbolAddress((void**)&p_wph, d_wph);
    cudaGetSymbolAddress((void**)&p_wg, d_wg);
    cudaGetSymbolAddress((void**)&p_ww, d_ww);

    const int GEMM2_SMEM = 4 * 4608 * 4;                             // 73728
    const int ATTN_SMEM = (2 * 64 * 132 + 2 * 8192 + 128 * 68) * 4;  // 167936
    cudaFuncSetAttribute(gemm2_k<256, true, 1>,  cudaFuncAttributeMaxDynamicSharedMemorySize, GEMM2_SMEM);
    cudaFuncSetAttribute(gemm2_k<256, true, 2>,  cudaFuncAttributeMaxDynamicSharedMemorySize, GEMM2_SMEM);
    cudaFuncSetAttribute(gemm2_k<256, false, 3>, cudaFuncAttributeMaxDynamicSharedMemorySize, GEMM2_SMEM);
    cudaFuncSetAttribute(gemm2_k<128, true, 0>,  cudaFuncAttributeMaxDynamicSharedMemorySize, GEMM2_SMEM);
    cudaFuncSetAttribute(attn_k, cudaFuncAttributeMaxDynamicSharedMemorySize, ATTN_SMEM);

    transpose_pack_k<<<dim3(HWN / 32, CC / 32, BB), 256>>>(x, p_xts, p_xtt);
    pack_split_k<<<(CI * CC / 2 + 255) / 256, 256>>>(th_w, p_wth, CI * CC / 2);
    pack_split_k<<<(CI * CC / 2 + 255) / 256, 256>>>(ph_w, p_wph, CI * CC / 2);
    pack_tf32_k<<<(CI * CC / 4 + 255) / 256, 256>>>(g_w, p_wg, CI * CC / 4);
    pack_split_k<<<(CC * CI / 2 + 255) / 256, 256>>>(W_w, p_ww, CC * CI / 2);

    // theta -> Q packed
    gemm2_k<256, true, 1><<<dim3(32, 1, BB), 256, GEMM2_SMEM>>>(
        p_xts, (long)HWN * CC, p_wth, th_b, (float*)p_qp, CI, (long)HWN * CI);
    // phi -> pooled K packed
    gemm2_k<256, true, 2><<<dim3(32, 1, BB), 256, GEMM2_SMEM>>>(
        p_xts, (long)HWN * CC, p_wph, ph_b, (float*)p_kp, CI, 0);
    // g -> pooled V packed (tf32 interleaved)
    gemm2_k<256, false, 3><<<dim3(32, 1, BB), 256, GEMM2_SMEM>>>(
        p_xtt, (long)HWN * CC, p_wg, g_b, (float*)p_vp, CI, 0);

    attn_k<<<dim3(HWN / 128, BB), 256, ATTN_SMEM>>>(p_qp, p_kp, p_vp, p_yp);

    gemm2_k<128, true, 0><<<dim3(32, 2, BB), 256, GEMM2_SMEM>>>(
        p_yp, (long)HWN * CI, p_ww, W_b, p_wy, CC, (long)HWN * CC);

    bnpart_k<<<256, 256>>>(p_wy);

    const int total = BB * CC * HWN;
    const int off = (out_size > total) ? (out_size - total) : 0;
    bnred_k<<<1, 256>>>(inp0, out, off);

    finalT_k<<<dim3(HWN / 32, CC / 32, BB), 256>>>(p_wy, x, gam, bet, out, off);
}